// round 1
// baseline (speedup 1.0000x reference)
#include <cuda_runtime.h>
#include <cstdint>

#define BATCH 512
#define T 128
#define C 384
#define H 6
#define D 64
#define HD (H*D)   // 384

typedef unsigned long long ull;

// ---------------- scratch (device globals; no runtime allocation) ----------------
__device__ __align__(256) float g_q[(size_t)BATCH * H * T * D];   // [b][h][t][d]
__device__ __align__(256) float g_k[(size_t)BATCH * H * T * D];
__device__ __align__(256) float g_v[(size_t)BATCH * H * T * D];
__device__ __align__(256) float g_att[(size_t)BATCH * T * HD];    // [b][t][h*D+d]

// ---------------- packed f32x2 helpers (FFMA2 path, PTX-only on sm_103a) ---------
__device__ __forceinline__ ull ffma2(ull a, ull b, ull c) {
    ull d;
    asm("fma.rn.f32x2 %0, %1, %2, %3;" : "=l"(d) : "l"(a), "l"(b), "l"(c));
    return d;
}
__device__ __forceinline__ ull fadd2(ull a, ull b) {
    ull d;
    asm("add.rn.f32x2 %0, %1, %2;" : "=l"(d) : "l"(a), "l"(b));
    return d;
}
__device__ __forceinline__ ull pack2(float lo, float hi) {
    ull r;
    asm("mov.b64 %0, {%1, %2};" : "=l"(r) : "f"(lo), "f"(hi));
    return r;
}
__device__ __forceinline__ void unpack2(ull v, float& lo, float& hi) {
    asm("mov.b64 {%0, %1}, %2;" : "=f"(lo), "=f"(hi) : "l"(v));
}

// =================================================================================
// Kernel 1: QKV projection.
// Per block: C_tile[128 x 128] = x_b[128 x 384] @ W[384 x 128-slice of 1152].
// n index maps to (which in {q,k,v}, head h, dim d): n = which*384 + h*64 + d.
// grid = (512, 9), 256 threads, each thread an 8x8 microtile (as 8x4 f32x2 pairs).
// A is stored in smem pre-duplicated into both f32x2 halves.
// =================================================================================
__global__ __launch_bounds__(256, 2)
void qkv_kernel(const float* __restrict__ x, const float* __restrict__ Wq,
                const float* __restrict__ Wk, const float* __restrict__ Wv)
{
    __shared__ __align__(16) ull   Asd[8][128];  // [k][m], value duplicated in both halves
    __shared__ __align__(16) float Bs[8][128];   // [k][n]

    const int b  = blockIdx.x;
    const int n0 = blockIdx.y * 128;          // 0..1151
    const int which = n0 / HD;                // 0=q, 1=k, 2=v (constant per tile)
    const int nw = n0 - which * HD;           // 0,128,256 within the which
    const float* __restrict__ W = (which == 0) ? Wq : (which == 1) ? Wk : Wv;

    const int tid = threadIdx.x;
    const int ty = tid >> 4;                  // 0..15
    const int tx = tid & 15;                  // 0..15
    const int tm = ty * 8;

    // cooperative loader indices
    const int a_row = tid >> 1;               // 0..127
    const int a_col = (tid & 1) * 4;          // 0 or 4
    const int b_row = tid >> 5;               // 0..7   (k within chunk)
    const int b_col = (tid & 31) * 4;         // 0..124 (n within tile)
    const int bn = nw + b_col;
    const int bh = bn >> 6;                   // head of this loader thread
    const int bd = bn & 63;

    const float* __restrict__ xA = x + (size_t)b * T * C + (size_t)a_row * C + a_col;
    const float* __restrict__ wB = W + ((size_t)bh * C + b_row) * D + bd;

    ull acc[8][4];
    #pragma unroll
    for (int i = 0; i < 8; i++)
        #pragma unroll
        for (int j = 0; j < 4; j++) acc[i][j] = 0ull;

    for (int k0 = 0; k0 < C; k0 += 8) {
        float4 av = *(const float4*)(xA + k0);
        Asd[a_col + 0][a_row] = pack2(av.x, av.x);
        Asd[a_col + 1][a_row] = pack2(av.y, av.y);
        Asd[a_col + 2][a_row] = pack2(av.z, av.z);
        Asd[a_col + 3][a_row] = pack2(av.w, av.w);
        float4 bv = *(const float4*)(wB + (size_t)k0 * D);
        *(float4*)&Bs[b_row][b_col] = bv;
        __syncthreads();

        #pragma unroll
        for (int kk = 0; kk < 8; kk++) {
            ull a2[8];
            #pragma unroll
            for (int i = 0; i < 4; i++) {
                ulonglong2 t2 = *(const ulonglong2*)&Asd[kk][tm + 2 * i];
                a2[2 * i] = t2.x; a2[2 * i + 1] = t2.y;
            }
            ull b2[4];
            {
                ulonglong2 t2 = *(const ulonglong2*)&Bs[kk][tx * 4];
                b2[0] = t2.x; b2[1] = t2.y;
                ulonglong2 t3 = *(const ulonglong2*)&Bs[kk][64 + tx * 4];
                b2[2] = t3.x; b2[3] = t3.y;
            }
            #pragma unroll
            for (int i = 0; i < 8; i++) {
                #pragma unroll
                for (int j = 0; j < 4; j++)
                    acc[i][j] = ffma2(a2[i], b2[j], acc[i][j]);
            }
        }
        __syncthreads();
    }

    // epilogue: two column groups g: cols g*64 + tx*4 .. +3, each inside one head
    #pragma unroll
    for (int g = 0; g < 2; g++) {
        const int h  = (nw >> 6) + g;
        const int d0 = tx * 4;
        float* outp = ((which == 0) ? g_q : (which == 1) ? g_k : g_v)
                    + ((size_t)(b * H + h) * T) * D + d0;
        #pragma unroll
        for (int i = 0; i < 8; i++) {
            float r0, r1, r2, r3;
            unpack2(acc[i][2 * g],     r0, r1);
            unpack2(acc[i][2 * g + 1], r2, r3);
            *(float4*)(outp + (size_t)(tm + i) * D) = make_float4(r0, r1, r2, r3);
        }
    }
}

// =================================================================================
// Kernel 2: causal attention per (b, h). 128 threads; thread t owns query row t.
// K,V staged in 64KB dynamic smem; scores computed online (no max-subtract:
// scores ~ N(0,1), fp32 exp is safe); out = sum(e*v)/sum(e).
// =================================================================================
__global__ __launch_bounds__(128)
void attn_kernel()
{
    extern __shared__ __align__(16) float sm[];
    float* ks = sm;                 // [128][64]
    float* vs = sm + T * D;         // [128][64]

    const int b = blockIdx.x;
    const int h = blockIdx.y;
    const int tid = threadIdx.x;

    const size_t base = (size_t)(b * H + h) * T * D;
    const float4* kg = (const float4*)(g_k + base);
    const float4* vg = (const float4*)(g_v + base);
    for (int i = tid; i < T * D / 4; i += 128) {
        ((float4*)ks)[i] = kg[i];
        ((float4*)vs)[i] = vg[i];
    }

    // this thread's query row (packed pairs)
    ull q2[32];
    const ulonglong2* qp = (const ulonglong2*)(g_q + base + (size_t)tid * D);
    #pragma unroll
    for (int i = 0; i < 16; i++) { ulonglong2 t2 = qp[i]; q2[2 * i] = t2.x; q2[2 * i + 1] = t2.y; }

    __syncthreads();

    ull acc[32];
    #pragma unroll
    for (int i = 0; i < 32; i++) acc[i] = 0ull;
    float denom = 0.f;

    const int t = tid;
    for (int s = 0; s <= t; s++) {
        const ulonglong2* kr = (const ulonglong2*)(ks + s * D);
        ull p0 = 0ull, p1 = 0ull, p2 = 0ull, p3 = 0ull;
        #pragma unroll
        for (int i = 0; i < 16; i += 2) {
            ulonglong2 ka = kr[i];
            ulonglong2 kb = kr[i + 1];
            p0 = ffma2(q2[2 * i],     ka.x, p0);
            p1 = ffma2(q2[2 * i + 1], ka.y, p1);
            p2 = ffma2(q2[2 * i + 2], kb.x, p2);
            p3 = ffma2(q2[2 * i + 3], kb.y, p3);
        }
        ull ps = fadd2(fadd2(p0, p1), fadd2(p2, p3));
        float lo, hi; unpack2(ps, lo, hi);
        const float e = __expf((lo + hi) * 0.125f);   // D^-0.5 = 1/8
        denom += e;
        const ull e2 = pack2(e, e);
        const ulonglong2* vr = (const ulonglong2*)(vs + s * D);
        #pragma unroll
        for (int i = 0; i < 16; i++) {
            ulonglong2 v2 = vr[i];
            acc[2 * i]     = ffma2(e2, v2.x, acc[2 * i]);
            acc[2 * i + 1] = ffma2(e2, v2.y, acc[2 * i + 1]);
        }
    }

    const float inv = 1.0f / denom;
    float* op = g_att + ((size_t)b * T + t) * HD + h * D;
    #pragma unroll
    for (int i = 0; i < 16; i++) {
        float r0, r1, r2, r3;
        unpack2(acc[2 * i],     r0, r1);
        unpack2(acc[2 * i + 1], r2, r3);
        *(float4*)(op + 4 * i) = make_float4(r0 * inv, r1 * inv, r2 * inv, r3 * inv);
    }
}

// =================================================================================
// Kernel 3: output projection. out[b,t,:] = att[b,t,:] @ Wp[384,384] + bp.
// Same 128x128x8 SGEMM structure as kernel 1. grid = (512, 3).
// =================================================================================
__global__ __launch_bounds__(256, 2)
void proj_kernel(const float* __restrict__ Wp, const float* __restrict__ bp,
                 float* __restrict__ out)
{
    __shared__ __align__(16) ull   Asd[8][128];
    __shared__ __align__(16) float Bs[8][128];

    const int b  = blockIdx.x;
    const int n0 = blockIdx.y * 128;

    const int tid = threadIdx.x;
    const int ty = tid >> 4, tx = tid & 15;
    const int tm = ty * 8;

    const int a_row = tid >> 1;
    const int a_col = (tid & 1) * 4;
    const int b_row = tid >> 5;
    const int b_col = (tid & 31) * 4;

    const float* __restrict__ xA = g_att + (size_t)b * T * HD + (size_t)a_row * HD + a_col;
    const float* __restrict__ wB = Wp + (size_t)b_row * HD + n0 + b_col;

    ull acc[8][4];
    #pragma unroll
    for (int i = 0; i < 8; i++)
        #pragma unroll
        for (int j = 0; j < 4; j++) acc[i][j] = 0ull;

    for (int k0 = 0; k0 < HD; k0 += 8) {
        float4 av = *(const float4*)(xA + k0);
        Asd[a_col + 0][a_row] = pack2(av.x, av.x);
        Asd[a_col + 1][a_row] = pack2(av.y, av.y);
        Asd[a_col + 2][a_row] = pack2(av.z, av.z);
        Asd[a_col + 3][a_row] = pack2(av.w, av.w);
        float4 bv = *(const float4*)(wB + (size_t)k0 * HD);
        *(float4*)&Bs[b_row][b_col] = bv;
        __syncthreads();

        #pragma unroll
        for (int kk = 0; kk < 8; kk++) {
            ull a2[8];
            #pragma unroll
            for (int i = 0; i < 4; i++) {
                ulonglong2 t2 = *(const ulonglong2*)&Asd[kk][tm + 2 * i];
                a2[2 * i] = t2.x; a2[2 * i + 1] = t2.y;
            }
            ull b2[4];
            {
                ulonglong2 t2 = *(const ulonglong2*)&Bs[kk][tx * 4];
                b2[0] = t2.x; b2[1] = t2.y;
                ulonglong2 t3 = *(const ulonglong2*)&Bs[kk][64 + tx * 4];
                b2[2] = t3.x; b2[3] = t3.y;
            }
            #pragma unroll
            for (int i = 0; i < 8; i++) {
                #pragma unroll
                for (int j = 0; j < 4; j++)
                    acc[i][j] = ffma2(a2[i], b2[j], acc[i][j]);
            }
        }
        __syncthreads();
    }

    #pragma unroll
    for (int g = 0; g < 2; g++) {
        const int n = n0 + g * 64 + tx * 4;
        const float4 bias = *(const float4*)(bp + n);
        float* outp = out + (size_t)b * T * HD + n;
        #pragma unroll
        for (int i = 0; i < 8; i++) {
            float r0, r1, r2, r3;
            unpack2(acc[i][2 * g],     r0, r1);
            unpack2(acc[i][2 * g + 1], r2, r3);
            *(float4*)(outp + (size_t)(tm + i) * HD) =
                make_float4(r0 + bias.x, r1 + bias.y, r2 + bias.z, r3 + bias.w);
        }
    }
}

// =================================================================================
extern "C" void kernel_launch(void* const* d_in, const int* in_sizes, int n_in,
                              void* d_out, int out_size)
{
    (void)in_sizes; (void)n_in; (void)out_size;
    const float* x  = (const float*)d_in[0];
    const float* Wq = (const float*)d_in[1];
    const float* Wk = (const float*)d_in[2];
    const float* Wv = (const float*)d_in[3];
    const float* Wp = (const float*)d_in[4];
    const float* bp = (const float*)d_in[5];
    float* out = (float*)d_out;

    // attn kernel needs 64KB dynamic smem (> 48KB default). Idempotent, capture-safe.
    cudaFuncSetAttribute(attn_kernel, cudaFuncAttributeMaxDynamicSharedMemorySize,
                         2 * T * D * (int)sizeof(float));

    qkv_kernel<<<dim3(BATCH, 9), 256>>>(x, Wq, Wk, Wv);
    attn_kernel<<<dim3(BATCH, H), 128, 2 * T * D * sizeof(float)>>>();
    proj_kernel<<<dim3(BATCH, 3), 256>>>(Wp, bp, out);
}

// round 3
// speedup vs baseline: 2.1090x; 2.1090x over previous
#include <cuda_runtime.h>
#include <cuda_bf16.h>
#include <cstdint>

#define BATCH 512
#define T 128
#define C 384
#define H 6
#define D 64
#define HD 384
#define NQKV 1152

typedef unsigned long long ull;

// ---------------- scratch (device globals; no runtime allocation) ----------------
__device__ __align__(256) float g_q[(size_t)BATCH * H * T * D];
__device__ __align__(256) float g_k[(size_t)BATCH * H * T * D];
__device__ __align__(256) float g_v[(size_t)BATCH * H * T * D];
__device__ __align__(256) __nv_bfloat16 g_xhi[(size_t)BATCH * T * C];
__device__ __align__(256) __nv_bfloat16 g_xlo[(size_t)BATCH * T * C];
__device__ __align__(256) __nv_bfloat16 g_wthi[(size_t)NQKV * C];   // [n][k]
__device__ __align__(256) __nv_bfloat16 g_wtlo[(size_t)NQKV * C];
__device__ __align__(256) __nv_bfloat16 g_wpthi[(size_t)HD * C];    // [n][k] = Wp[k][n]
__device__ __align__(256) __nv_bfloat16 g_wptlo[(size_t)HD * C];
__device__ __align__(256) __nv_bfloat16 g_atthi[(size_t)BATCH * T * HD];
__device__ __align__(256) __nv_bfloat16 g_attlo[(size_t)BATCH * T * HD];

// ---------------- packed f32x2 helpers (attn kernel) ----------------
__device__ __forceinline__ ull ffma2(ull a, ull b, ull c) {
    ull d;
    asm("fma.rn.f32x2 %0, %1, %2, %3;" : "=l"(d) : "l"(a), "l"(b), "l"(c));
    return d;
}
__device__ __forceinline__ ull fadd2(ull a, ull b) {
    ull d;
    asm("add.rn.f32x2 %0, %1, %2;" : "=l"(d) : "l"(a), "l"(b));
    return d;
}
__device__ __forceinline__ ull pack2(float lo, float hi) {
    ull r;
    asm("mov.b64 %0, {%1, %2};" : "=l"(r) : "f"(lo), "f"(hi));
    return r;
}
__device__ __forceinline__ void unpack2(ull v, float& lo, float& hi) {
    asm("mov.b64 {%0, %1}, %2;" : "=f"(lo), "=f"(hi) : "l"(v));
}

// ---------------- mma.sync / ldmatrix / cp.async (baseline PTX, compute_103-safe) ----
__device__ __forceinline__ uint32_t smem_u32(const void* p) {
    uint32_t a;
    asm("{ .reg .u64 t; cvta.to.shared.u64 t, %1; cvt.u32.u64 %0, t; }" : "=r"(a) : "l"(p));
    return a;
}
__device__ __forceinline__ void ldsm4(uint32_t* r, uint32_t addr) {
    asm volatile("ldmatrix.sync.aligned.m8n8.x4.shared.b16 {%0,%1,%2,%3}, [%4];"
        : "=r"(r[0]), "=r"(r[1]), "=r"(r[2]), "=r"(r[3]) : "r"(addr));
}
__device__ __forceinline__ void mma16816(float* c, const uint32_t* a, const uint32_t* b) {
    asm volatile("mma.sync.aligned.m16n8k16.row.col.f32.bf16.bf16.f32 "
        "{%0,%1,%2,%3}, {%4,%5,%6,%7}, {%8,%9}, {%0,%1,%2,%3};"
        : "+f"(c[0]), "+f"(c[1]), "+f"(c[2]), "+f"(c[3])
        : "r"(a[0]), "r"(a[1]), "r"(a[2]), "r"(a[3]), "r"(b[0]), "r"(b[1]));
}
__device__ __forceinline__ void cpa16(uint32_t dst, const void* src) {
    asm volatile("cp.async.cg.shared.global [%0], [%1], 16;" :: "r"(dst), "l"(src));
}
#define CPA_COMMIT() asm volatile("cp.async.commit_group;" ::: "memory")
#define CPA_WAIT1()  asm volatile("cp.async.wait_group 1;" ::: "memory")
#define CPA_WAIT0()  asm volatile("cp.async.wait_group 0;" ::: "memory")

// =================================================================================
// Conversion kernels (fp32 -> bf16 hi/lo split)
// =================================================================================
__global__ void conv_x_kernel(const float* __restrict__ x) {
    size_t i = ((size_t)blockIdx.x * 256 + threadIdx.x) * 4;
    float4 v = *(const float4*)(x + i);
    __nv_bfloat16 h0 = __float2bfloat16(v.x), h1 = __float2bfloat16(v.y);
    __nv_bfloat16 h2 = __float2bfloat16(v.z), h3 = __float2bfloat16(v.w);
    __nv_bfloat162 p;
    p.x = h0; p.y = h1; *(__nv_bfloat162*)(g_xhi + i)     = p;
    p.x = h2; p.y = h3; *(__nv_bfloat162*)(g_xhi + i + 2) = p;
    p.x = __float2bfloat16(v.x - __bfloat162float(h0));
    p.y = __float2bfloat16(v.y - __bfloat162float(h1));
    *(__nv_bfloat162*)(g_xlo + i) = p;
    p.x = __float2bfloat16(v.z - __bfloat162float(h2));
    p.y = __float2bfloat16(v.w - __bfloat162float(h3));
    *(__nv_bfloat162*)(g_xlo + i + 2) = p;
}

__global__ void conv_w_kernel(const float* __restrict__ Wq, const float* __restrict__ Wk,
                              const float* __restrict__ Wv) {
    int idx = blockIdx.x * 256 + threadIdx.x;   // n*C + k
    if (idx >= NQKV * C) return;
    int n = idx / C, k = idx - n * C;
    int which = n / HD, rem = n - which * HD;
    int h = rem >> 6, d = rem & 63;
    const float* W = (which == 0) ? Wq : (which == 1) ? Wk : Wv;
    float v = W[((size_t)h * C + k) * D + d];
    __nv_bfloat16 hi = __float2bfloat16(v);
    g_wthi[idx] = hi;
    g_wtlo[idx] = __float2bfloat16(v - __bfloat162float(hi));
}

__global__ void conv_wp_kernel(const float* __restrict__ Wp) {
    int idx = blockIdx.x * 256 + threadIdx.x;   // n*C + k
    if (idx >= HD * C) return;
    int n = idx / C, k = idx - n * C;
    float v = Wp[(size_t)k * C + n];
    __nv_bfloat16 hi = __float2bfloat16(v);
    g_wpthi[idx] = hi;
    g_wptlo[idx] = __float2bfloat16(v - __bfloat162float(hi));
}

// =================================================================================
// Tensor-core GEMM via mma.sync: Y[128 x 128] = A[128 x 384] @ B[n][k]^T, bf16 3-split.
// K in 6 chunks of 64; cp.async double-buffered smem; ldmatrix fragment loads.
// Stage layout (64KB): Ahi @0, Alo @16384, Bhi @32768, Blo @49152; 2 stages.
// 8 warps as 2(m) x 4(n); warp tile 64x32 -> 4 m-frags x 4 n-frags.
// =================================================================================
#define STAGE_BYTES 65536
#define MMA_SMEM (2 * STAGE_BYTES)

template <bool PROJ>
__global__ __launch_bounds__(256, 1)
void mma_gemm(const float* __restrict__ bp, float* __restrict__ out)
{
    extern __shared__ __align__(1024) char sm[];
    const uint32_t smb = smem_u32(sm);
    const int tid = threadIdx.x, wid = tid >> 5, lane = tid & 31;
    const int b = blockIdx.x, n0 = blockIdx.y * 128;
    const int wm = (wid >> 2) * 64;     // 0 or 64
    const int wn = (wid & 3) * 32;      // 0,32,64,96

    const __nv_bfloat16* __restrict__ Ahi = (PROJ ? g_atthi : g_xhi) + (size_t)b * T * C;
    const __nv_bfloat16* __restrict__ Alo = (PROJ ? g_attlo : g_xlo) + (size_t)b * T * C;
    const __nv_bfloat16* __restrict__ Bhi = (PROJ ? g_wpthi : g_wthi) + (size_t)n0 * C;
    const __nv_bfloat16* __restrict__ Blo = (PROJ ? g_wptlo : g_wtlo) + (size_t)n0 * C;

    // loader: thread -> (row, seg); 4 passes cover 128 rows x 8 segs of 16B
    const int l_row = tid >> 3;          // 0..31 (+32 per pass)
    const int l_seg = tid & 7;

    auto load_chunk = [&](int c, int s) {
        const int c0 = c * 64;
        const uint32_t sb = smb + s * STAGE_BYTES;
#pragma unroll
        for (int p = 0; p < 4; p++) {
            const int row = l_row + p * 32;
            const uint32_t doff = (uint32_t)(row * 128 + ((l_seg ^ (row & 7)) << 4));
            const size_t soff = (size_t)row * C + c0 + l_seg * 8;
            cpa16(sb + doff,         Ahi + soff);
            cpa16(sb + 16384 + doff, Alo + soff);
            cpa16(sb + 32768 + doff, Bhi + soff);
            cpa16(sb + 49152 + doff, Blo + soff);
        }
        CPA_COMMIT();
    };

    float acc[4][4][4];
#pragma unroll
    for (int i = 0; i < 4; i++)
#pragma unroll
        for (int j = 0; j < 4; j++)
#pragma unroll
            for (int e = 0; e < 4; e++) acc[i][j][e] = 0.f;

    // ldmatrix per-lane geometry
    const int rA  = (lane & 7) + ((lane >> 3) & 1) * 8;  // A: mats (m0k0),(m8k0),(m0k8),(m8k8)
    const int khA = lane >> 4;
    const int swA = rA & 7;
    const int rB  = (lane & 7) + (lane >> 4) * 8;        // B: mats (n0k0),(n0k8),(n8k0),(n8k8)
    const int khB = (lane >> 3) & 1;
    const int swB = rB & 7;

    load_chunk(0, 0);
    load_chunk(1, 1);

    for (int c = 0; c < 6; c++) {
        if (c == 5) CPA_WAIT0(); else CPA_WAIT1();
        __syncthreads();

        const uint32_t sb = smb + (c & 1) * STAGE_BYTES;
        const uint32_t aBase = sb + (uint32_t)((wm + rA) * 128);
        const uint32_t bBase = sb + 32768 + (uint32_t)((wn + rB) * 128);

#pragma unroll
        for (int ks = 0; ks < 4; ks++) {
            const uint32_t aoff = (uint32_t)(((ks * 2 + khA) ^ swA) << 4);
            const uint32_t boff = (uint32_t)(((ks * 2 + khB) ^ swB) << 4);
            uint32_t ahi[4][4], alo[4][4], bh[2][4], bl[2][4];
#pragma unroll
            for (int mf = 0; mf < 4; mf++) {
                ldsm4(ahi[mf], aBase + mf * 2048 + aoff);
                ldsm4(alo[mf], aBase + 16384 + mf * 2048 + aoff);
            }
#pragma unroll
            for (int g = 0; g < 2; g++) {
                ldsm4(bh[g], bBase + g * 2048 + boff);
                ldsm4(bl[g], bBase + 16384 + g * 2048 + boff);
            }
#pragma unroll
            for (int mf = 0; mf < 4; mf++) {
#pragma unroll
                for (int nf = 0; nf < 4; nf++) {
                    const uint32_t* bhf = &bh[nf >> 1][(nf & 1) * 2];
                    const uint32_t* blf = &bl[nf >> 1][(nf & 1) * 2];
                    mma16816(acc[mf][nf], ahi[mf], bhf);
                    mma16816(acc[mf][nf], ahi[mf], blf);
                    mma16816(acc[mf][nf], alo[mf], bhf);
                }
            }
        }
        __syncthreads();
        if (c + 2 < 6) load_chunk(c + 2, (c & 1));
    }

    // ---------------- epilogue ----------------
    const int qrow = lane >> 2;
    const int qcol = (lane & 3) * 2;

    if (PROJ) {
#pragma unroll
        for (int mf = 0; mf < 4; mf++) {
#pragma unroll
            for (int nf = 0; nf < 4; nf++) {
                const int row = wm + mf * 16 + qrow;
                const int col = n0 + wn + nf * 8 + qcol;
                const float2 bb = *(const float2*)(bp + col);
                float* p0 = out + ((size_t)b * T + row) * HD + col;
                float* p1 = out + ((size_t)b * T + row + 8) * HD + col;
                *(float2*)p0 = make_float2(acc[mf][nf][0] + bb.x, acc[mf][nf][1] + bb.y);
                *(float2*)p1 = make_float2(acc[mf][nf][2] + bb.x, acc[mf][nf][3] + bb.y);
            }
        }
    } else {
        const int which = n0 / HD;
        const int remBase = n0 - which * HD;
        float* base = (which == 0) ? g_q : (which == 1) ? g_k : g_v;
#pragma unroll
        for (int mf = 0; mf < 4; mf++) {
#pragma unroll
            for (int nf = 0; nf < 4; nf++) {
                const int row = wm + mf * 16 + qrow;
                const int rem = remBase + wn + nf * 8 + qcol;
                const int h = rem >> 6, d = rem & 63;
                float* p0 = base + (((size_t)(b * H + h) * T) + row) * D + d;
                float* p1 = base + (((size_t)(b * H + h) * T) + row + 8) * D + d;
                *(float2*)p0 = make_float2(acc[mf][nf][0], acc[mf][nf][1]);
                *(float2*)p1 = make_float2(acc[mf][nf][2], acc[mf][nf][3]);
            }
        }
    }
}

// =================================================================================
// Attention per (b, h). 128 threads; thread t owns query row t (FFMA2 path).
// Emits bf16 hi/lo of the attention output for the proj GEMM.
// =================================================================================
__global__ __launch_bounds__(128)
void attn_kernel()
{
    extern __shared__ __align__(16) float smf[];
    float* ks = smf;
    float* vs = smf + T * D;

    const int b = blockIdx.x;
    const int h = blockIdx.y;
    const int tid = threadIdx.x;

    const size_t base = (size_t)(b * H + h) * T * D;
    const float4* kg = (const float4*)(g_k + base);
    const float4* vg = (const float4*)(g_v + base);
    for (int i = tid; i < T * D / 4; i += 128) {
        ((float4*)ks)[i] = kg[i];
        ((float4*)vs)[i] = vg[i];
    }

    ull q2[32];
    const ulonglong2* qp = (const ulonglong2*)(g_q + base + (size_t)tid * D);
#pragma unroll
    for (int i = 0; i < 16; i++) { ulonglong2 t2 = qp[i]; q2[2 * i] = t2.x; q2[2 * i + 1] = t2.y; }

    __syncthreads();

    ull acc[32];
#pragma unroll
    for (int i = 0; i < 32; i++) acc[i] = 0ull;
    float denom = 0.f;

    const int t = tid;
    for (int s = 0; s <= t; s++) {
        const ulonglong2* kr = (const ulonglong2*)(ks + s * D);
        ull p0 = 0ull, p1 = 0ull, p2 = 0ull, p3 = 0ull;
#pragma unroll
        for (int i = 0; i < 16; i += 2) {
            ulonglong2 ka = kr[i];
            ulonglong2 kb = kr[i + 1];
            p0 = ffma2(q2[2 * i],     ka.x, p0);
            p1 = ffma2(q2[2 * i + 1], ka.y, p1);
            p2 = ffma2(q2[2 * i + 2], kb.x, p2);
            p3 = ffma2(q2[2 * i + 3], kb.y, p3);
        }
        ull ps = fadd2(fadd2(p0, p1), fadd2(p2, p3));
        float lo, hi; unpack2(ps, lo, hi);
        const float e = __expf((lo + hi) * 0.125f);
        denom += e;
        const ull e2 = pack2(e, e);
        const ulonglong2* vr = (const ulonglong2*)(vs + s * D);
#pragma unroll
        for (int i = 0; i < 16; i++) {
            ulonglong2 v2 = vr[i];
            acc[2 * i]     = ffma2(e2, v2.x, acc[2 * i]);
            acc[2 * i + 1] = ffma2(e2, v2.y, acc[2 * i + 1]);
        }
    }

    const float inv = 1.0f / denom;
    __nv_bfloat16* oh = g_atthi + ((size_t)b * T + t) * HD + h * D;
    __nv_bfloat16* ol = g_attlo + ((size_t)b * T + t) * HD + h * D;
#pragma unroll
    for (int i = 0; i < 16; i++) {
        float r0, r1, r2, r3;
        unpack2(acc[2 * i],     r0, r1);
        unpack2(acc[2 * i + 1], r2, r3);
        r0 *= inv; r1 *= inv; r2 *= inv; r3 *= inv;
        __nv_bfloat16 h0 = __float2bfloat16(r0), h1 = __float2bfloat16(r1);
        __nv_bfloat16 h2 = __float2bfloat16(r2), h3 = __float2bfloat16(r3);
        __nv_bfloat162 ph;
        ph.x = h0; ph.y = h1; *(__nv_bfloat162*)(oh + 4 * i)     = ph;
        ph.x = h2; ph.y = h3; *(__nv_bfloat162*)(oh + 4 * i + 2) = ph;
        __nv_bfloat162 pl;
        pl.x = __float2bfloat16(r0 - __bfloat162float(h0));
        pl.y = __float2bfloat16(r1 - __bfloat162float(h1));
        *(__nv_bfloat162*)(ol + 4 * i) = pl;
        pl.x = __float2bfloat16(r2 - __bfloat162float(h2));
        pl.y = __float2bfloat16(r3 - __bfloat162float(h3));
        *(__nv_bfloat162*)(ol + 4 * i + 2) = pl;
    }
}

// =================================================================================
extern "C" void kernel_launch(void* const* d_in, const int* in_sizes, int n_in,
                              void* d_out, int out_size)
{
    (void)in_sizes; (void)n_in; (void)out_size;
    const float* x  = (const float*)d_in[0];
    const float* Wq = (const float*)d_in[1];
    const float* Wk = (const float*)d_in[2];
    const float* Wv = (const float*)d_in[3];
    const float* Wp = (const float*)d_in[4];
    const float* bp = (const float*)d_in[5];
    float* out = (float*)d_out;

    cudaFuncSetAttribute(mma_gemm<false>, cudaFuncAttributeMaxDynamicSharedMemorySize, MMA_SMEM);
    cudaFuncSetAttribute(mma_gemm<true>,  cudaFuncAttributeMaxDynamicSharedMemorySize, MMA_SMEM);
    cudaFuncSetAttribute(attn_kernel, cudaFuncAttributeMaxDynamicSharedMemorySize,
                         2 * T * D * (int)sizeof(float));

    conv_x_kernel<<<(BATCH * T * C / 4) / 256, 256>>>(x);
    conv_w_kernel<<<(NQKV * C + 255) / 256, 256>>>(Wq, Wk, Wv);
    conv_wp_kernel<<<(HD * C + 255) / 256, 256>>>(Wp);

    mma_gemm<false><<<dim3(BATCH, 9), 256, MMA_SMEM>>>(nullptr, nullptr);
    attn_kernel<<<dim3(BATCH, H), 128, 2 * T * D * sizeof(float)>>>();
    mma_gemm<true><<<dim3(BATCH, 3), 256, MMA_SMEM>>>(bp, out);
}

// round 4
// speedup vs baseline: 2.8141x; 1.3343x over previous
#include <cuda_runtime.h>
#include <cuda_bf16.h>
#include <cstdint>

#define BATCH 512
#define T 128
#define C 384
#define H 6
#define D 64
#define HD 384
#define NQKV 1152

typedef unsigned long long ull;

// ---------------- scratch (device globals; no runtime allocation) ----------------
__device__ __align__(256) __nv_bfloat16 g_xhi[(size_t)BATCH * T * C];
__device__ __align__(256) __nv_bfloat16 g_xlo[(size_t)BATCH * T * C];
__device__ __align__(256) __nv_bfloat16 g_wthi[(size_t)NQKV * C];   // [n][k]
__device__ __align__(256) __nv_bfloat16 g_wtlo[(size_t)NQKV * C];
__device__ __align__(256) __nv_bfloat16 g_wpthi[(size_t)HD * C];    // [n][k] = Wp[k][n]
__device__ __align__(256) __nv_bfloat16 g_wptlo[(size_t)HD * C];
// q,k: [b][h][t][d]; v transposed: [b][h][d][t]
__device__ __align__(256) __nv_bfloat16 g_qhi[(size_t)BATCH * H * T * D];
__device__ __align__(256) __nv_bfloat16 g_qlo[(size_t)BATCH * H * T * D];
__device__ __align__(256) __nv_bfloat16 g_khi[(size_t)BATCH * H * T * D];
__device__ __align__(256) __nv_bfloat16 g_klo[(size_t)BATCH * H * T * D];
__device__ __align__(256) __nv_bfloat16 g_vthi[(size_t)BATCH * H * T * D];
__device__ __align__(256) __nv_bfloat16 g_vtlo[(size_t)BATCH * H * T * D];
__device__ __align__(256) __nv_bfloat16 g_atthi[(size_t)BATCH * T * HD];
__device__ __align__(256) __nv_bfloat16 g_attlo[(size_t)BATCH * T * HD];

// ---------------- helpers (baseline PTX, compute_103-safe) ----------------
__device__ __forceinline__ uint32_t smem_u32(const void* p) {
    uint32_t a;
    asm("{ .reg .u64 t; cvta.to.shared.u64 t, %1; cvt.u32.u64 %0, t; }" : "=r"(a) : "l"(p));
    return a;
}
__device__ __forceinline__ void ldsm4(uint32_t* r, uint32_t addr) {
    asm volatile("ldmatrix.sync.aligned.m8n8.x4.shared.b16 {%0,%1,%2,%3}, [%4];"
        : "=r"(r[0]), "=r"(r[1]), "=r"(r[2]), "=r"(r[3]) : "r"(addr));
}
__device__ __forceinline__ void mma16816(float* c, const uint32_t* a, const uint32_t* b) {
    asm volatile("mma.sync.aligned.m16n8k16.row.col.f32.bf16.bf16.f32 "
        "{%0,%1,%2,%3}, {%4,%5,%6,%7}, {%8,%9}, {%0,%1,%2,%3};"
        : "+f"(c[0]), "+f"(c[1]), "+f"(c[2]), "+f"(c[3])
        : "r"(a[0]), "r"(a[1]), "r"(a[2]), "r"(a[3]), "r"(b[0]), "r"(b[1]));
}
__device__ __forceinline__ void cpa16(uint32_t dst, const void* src) {
    asm volatile("cp.async.cg.shared.global [%0], [%1], 16;" :: "r"(dst), "l"(src));
}
#define CPA_COMMIT() asm volatile("cp.async.commit_group;" ::: "memory")
#define CPA_WAIT1()  asm volatile("cp.async.wait_group 1;" ::: "memory")
#define CPA_WAIT0()  asm volatile("cp.async.wait_group 0;" ::: "memory")

// pack two f32 -> bf16x2 (lo in low half), and hi/lo split helpers
__device__ __forceinline__ uint32_t cvt_bf16x2(float lo, float hi) {
    uint32_t r;
    asm("cvt.rn.bf16x2.f32 %0, %1, %2;" : "=r"(r) : "f"(hi), "f"(lo));
    return r;
}
__device__ __forceinline__ float lo_f(uint32_t u) { return __uint_as_float(u << 16); }
__device__ __forceinline__ float hi_f(uint32_t u) { return __uint_as_float(u & 0xFFFF0000u); }
__device__ __forceinline__ void hilo_pair(float a, float b, uint32_t& h, uint32_t& l) {
    h = cvt_bf16x2(a, b);
    l = cvt_bf16x2(a - lo_f(h), b - hi_f(h));
}

// =================================================================================
// Conversion kernels (fp32 -> bf16 hi/lo split)
// =================================================================================
__global__ void conv_x_kernel(const float* __restrict__ x) {
    size_t i = ((size_t)blockIdx.x * 256 + threadIdx.x) * 4;
    float4 v = *(const float4*)(x + i);
    uint32_t h0, l0, h1, l1;
    hilo_pair(v.x, v.y, h0, l0);
    hilo_pair(v.z, v.w, h1, l1);
    *(uint32_t*)(g_xhi + i)     = h0;
    *(uint32_t*)(g_xhi + i + 2) = h1;
    *(uint32_t*)(g_xlo + i)     = l0;
    *(uint32_t*)(g_xlo + i + 2) = l1;
}

__global__ void conv_w_kernel(const float* __restrict__ Wq, const float* __restrict__ Wk,
                              const float* __restrict__ Wv) {
    int idx = blockIdx.x * 256 + threadIdx.x;   // n*C + k
    if (idx >= NQKV * C) return;
    int n = idx / C, k = idx - n * C;
    int which = n / HD, rem = n - which * HD;
    int h = rem >> 6, d = rem & 63;
    const float* W = (which == 0) ? Wq : (which == 1) ? Wk : Wv;
    float v = W[((size_t)h * C + k) * D + d];
    __nv_bfloat16 hi = __float2bfloat16(v);
    g_wthi[idx] = hi;
    g_wtlo[idx] = __float2bfloat16(v - __bfloat162float(hi));
}

__global__ void conv_wp_kernel(const float* __restrict__ Wp) {
    int idx = blockIdx.x * 256 + threadIdx.x;   // n*C + k
    if (idx >= HD * C) return;
    int n = idx / C, k = idx - n * C;
    float v = Wp[(size_t)k * C + n];
    __nv_bfloat16 hi = __float2bfloat16(v);
    g_wpthi[idx] = hi;
    g_wptlo[idx] = __float2bfloat16(v - __bfloat162float(hi));
}

// =================================================================================
// Tensor-core GEMM: Y[128 x 128] = A[128 x 384] @ B[n][k]^T, bf16 3-split.
// PROJ=false: A = x hi/lo, B = wt; epilogue writes q/k bf16 hi/lo and v TRANSPOSED.
// PROJ=true : A = att hi/lo, B = wpt; epilogue adds bias, writes fp32 out.
// =================================================================================
#define STAGE_BYTES 65536
#define MMA_SMEM (2 * STAGE_BYTES)

template <bool PROJ>
__global__ __launch_bounds__(256, 1)
void mma_gemm(const float* __restrict__ bp, float* __restrict__ out)
{
    extern __shared__ __align__(1024) char sm[];
    const uint32_t smb = smem_u32(sm);
    const int tid = threadIdx.x, wid = tid >> 5, lane = tid & 31;
    const int b = blockIdx.x, n0 = blockIdx.y * 128;
    const int wm = (wid >> 2) * 64;     // 0 or 64
    const int wn = (wid & 3) * 32;      // 0,32,64,96

    const __nv_bfloat16* __restrict__ Ahi = (PROJ ? g_atthi : g_xhi) + (size_t)b * T * C;
    const __nv_bfloat16* __restrict__ Alo = (PROJ ? g_attlo : g_xlo) + (size_t)b * T * C;
    const __nv_bfloat16* __restrict__ Bhi = (PROJ ? g_wpthi : g_wthi) + (size_t)n0 * C;
    const __nv_bfloat16* __restrict__ Blo = (PROJ ? g_wptlo : g_wtlo) + (size_t)n0 * C;

    const int l_row = tid >> 3;          // 0..31 (+32 per pass)
    const int l_seg = tid & 7;

    auto load_chunk = [&](int c, int s) {
        const int c0 = c * 64;
        const uint32_t sb = smb + s * STAGE_BYTES;
#pragma unroll
        for (int p = 0; p < 4; p++) {
            const int row = l_row + p * 32;
            const uint32_t doff = (uint32_t)(row * 128 + ((l_seg ^ (row & 7)) << 4));
            const size_t soff = (size_t)row * C + c0 + l_seg * 8;
            cpa16(sb + doff,         Ahi + soff);
            cpa16(sb + 16384 + doff, Alo + soff);
            cpa16(sb + 32768 + doff, Bhi + soff);
            cpa16(sb + 49152 + doff, Blo + soff);
        }
        CPA_COMMIT();
    };

    float acc[4][4][4];
#pragma unroll
    for (int i = 0; i < 4; i++)
#pragma unroll
        for (int j = 0; j < 4; j++)
#pragma unroll
            for (int e = 0; e < 4; e++) acc[i][j][e] = 0.f;

    const int rA  = (lane & 7) + ((lane >> 3) & 1) * 8;
    const int khA = lane >> 4;
    const int swA = rA & 7;
    const int rB  = (lane & 7) + (lane >> 4) * 8;
    const int khB = (lane >> 3) & 1;
    const int swB = rB & 7;

    load_chunk(0, 0);
    load_chunk(1, 1);

    for (int c = 0; c < 6; c++) {
        if (c == 5) CPA_WAIT0(); else CPA_WAIT1();
        __syncthreads();

        const uint32_t sb = smb + (c & 1) * STAGE_BYTES;
        const uint32_t aBase = sb + (uint32_t)((wm + rA) * 128);
        const uint32_t bBase = sb + 32768 + (uint32_t)((wn + rB) * 128);

#pragma unroll
        for (int ks = 0; ks < 4; ks++) {
            const uint32_t aoff = (uint32_t)(((ks * 2 + khA) ^ swA) << 4);
            const uint32_t boff = (uint32_t)(((ks * 2 + khB) ^ swB) << 4);
            uint32_t ahi[4][4], alo[4][4], bh[2][4], bl[2][4];
#pragma unroll
            for (int mf = 0; mf < 4; mf++) {
                ldsm4(ahi[mf], aBase + mf * 2048 + aoff);
                ldsm4(alo[mf], aBase + 16384 + mf * 2048 + aoff);
            }
#pragma unroll
            for (int g = 0; g < 2; g++) {
                ldsm4(bh[g], bBase + g * 2048 + boff);
                ldsm4(bl[g], bBase + 16384 + g * 2048 + boff);
            }
#pragma unroll
            for (int mf = 0; mf < 4; mf++) {
#pragma unroll
                for (int nf = 0; nf < 4; nf++) {
                    const uint32_t* bhf = &bh[nf >> 1][(nf & 1) * 2];
                    const uint32_t* blf = &bl[nf >> 1][(nf & 1) * 2];
                    mma16816(acc[mf][nf], ahi[mf], bhf);
                    mma16816(acc[mf][nf], ahi[mf], blf);
                    mma16816(acc[mf][nf], alo[mf], bhf);
                }
            }
        }
        __syncthreads();
        if (c + 2 < 6) load_chunk(c + 2, (c & 1));
    }

    // ---------------- epilogue ----------------
    const int qrow = lane >> 2;
    const int qcol = (lane & 3) * 2;

    if (PROJ) {
#pragma unroll
        for (int mf = 0; mf < 4; mf++) {
#pragma unroll
            for (int nf = 0; nf < 4; nf++) {
                const int row = wm + mf * 16 + qrow;
                const int col = n0 + wn + nf * 8 + qcol;
                const float2 bb = *(const float2*)(bp + col);
                float* p0 = out + ((size_t)b * T + row) * HD + col;
                float* p1 = out + ((size_t)b * T + row + 8) * HD + col;
                *(float2*)p0 = make_float2(acc[mf][nf][0] + bb.x, acc[mf][nf][1] + bb.y);
                *(float2*)p1 = make_float2(acc[mf][nf][2] + bb.x, acc[mf][nf][3] + bb.y);
            }
        }
    } else {
        const int which = n0 / HD;
        const int remBase = n0 - which * HD;
#pragma unroll
        for (int mf = 0; mf < 4; mf++) {
#pragma unroll
            for (int nf = 0; nf < 4; nf++) {
                const int row = wm + mf * 16 + qrow;
                const int rem = remBase + wn + nf * 8 + qcol;
                const int hh = rem >> 6, dd = rem & 63;
                if (which < 2) {
                    __nv_bfloat16* bh_ = (which == 0) ? g_qhi : g_khi;
                    __nv_bfloat16* bl_ = (which == 0) ? g_qlo : g_klo;
                    const size_t o0 = (((size_t)(b * H + hh) * T) + row) * D + dd;
                    uint32_t hi, lo;
                    hilo_pair(acc[mf][nf][0], acc[mf][nf][1], hi, lo);
                    *(uint32_t*)(bh_ + o0) = hi;
                    *(uint32_t*)(bl_ + o0) = lo;
                    hilo_pair(acc[mf][nf][2], acc[mf][nf][3], hi, lo);
                    *(uint32_t*)(bh_ + o0 + 8 * D) = hi;
                    *(uint32_t*)(bl_ + o0 + 8 * D) = lo;
                } else {
                    // v transposed: [b][h][d][t], scalar bf16 stores
#pragma unroll
                    for (int e = 0; e < 4; e++) {
                        const int rr = row + (e >> 1) * 8;
                        const int dc = dd + (e & 1);
                        const float v = acc[mf][nf][e];
                        const __nv_bfloat16 hb = __float2bfloat16(v);
                        const size_t o = ((size_t)(b * H + hh) * D + dc) * T + rr;
                        g_vthi[o] = hb;
                        g_vtlo[o] = __float2bfloat16(v - __bfloat162float(hb));
                    }
                }
            }
        }
    }
}

// =================================================================================
// MMA attention per (b, h). 8 warps; warp owns 16 query rows (block rb, remapped
// for SMSP load balance). S = Q@K^T 3-split -> softmax (no max-sub) -> P hi/lo in
// regs -> O = P@V 3-split with transposed V. Causal block-skip: g<=rb, ks<=rb.
// smem: qhi 0, qlo 16K, khi 32K, klo 48K, v0hi 64K, v0lo 72K, v1hi 80K, v1lo 88K.
// =================================================================================
#define ATTN_SMEM 98304

__global__ __launch_bounds__(256, 1)
void attn_mma()
{
    extern __shared__ __align__(1024) char sm[];
    const uint32_t smb = smem_u32(sm);
    const int tid = threadIdx.x, w = tid >> 5, lane = tid & 31;
    const int b = blockIdx.x, h = blockIdx.y;
    const int rb = (w < 4) ? w : (11 - w);     // row-block; SMSP pairs balanced

    const size_t blk = (size_t)(b * H + h) * (T * D);
    const __nv_bfloat16* __restrict__ qhiG = g_qhi + blk;
    const __nv_bfloat16* __restrict__ qloG = g_qlo + blk;
    const __nv_bfloat16* __restrict__ khiG = g_khi + blk;
    const __nv_bfloat16* __restrict__ kloG = g_klo + blk;
    const __nv_bfloat16* __restrict__ vthiG = g_vthi + blk;
    const __nv_bfloat16* __restrict__ vtloG = g_vtlo + blk;

    {
        const int seg = tid & 7;
#pragma unroll
        for (int p = 0; p < 4; p++) {
            const int row = (tid + p * 256) >> 3;          // 0..127
            const uint32_t doff = (uint32_t)(row * 128 + ((seg ^ (row & 7)) << 4));
            const size_t soff = (size_t)row * D + seg * 8;
            cpa16(smb + doff,         qhiG + soff);
            cpa16(smb + 16384 + doff, qloG + soff);
            cpa16(smb + 32768 + doff, khiG + soff);
            cpa16(smb + 49152 + doff, kloG + soff);
        }
#pragma unroll
        for (int p = 0; p < 2; p++) {
            const int row = (tid + p * 256) >> 3;          // 0..63 (d)
            const uint32_t doff = (uint32_t)(row * 128 + ((seg ^ (row & 7)) << 4));
            const size_t s0 = (size_t)row * T + seg * 8;   // vt row d, s segment
            cpa16(smb + 65536 + doff, vthiG + s0);
            cpa16(smb + 73728 + doff, vtloG + s0);
            cpa16(smb + 81920 + doff, vthiG + s0 + 64);
            cpa16(smb + 90112 + doff, vtloG + s0 + 64);
        }
    }
    CPA_COMMIT();
    CPA_WAIT0();
    __syncthreads();

    const int rA  = (lane & 7) + ((lane >> 3) & 1) * 8;
    const int khA = lane >> 4;
    const int swA = rA & 7;
    const int rB  = (lane & 7) + (lane >> 4) * 8;
    const int khB = (lane >> 3) & 1;
    const int swB = rB & 7;

    const uint32_t aQhi = smb + (uint32_t)((rb * 16 + rA) * 128);
    const uint32_t aQlo = aQhi + 16384;

    // ---------------- S = Q @ K^T (3-split, causal block-skip) ----------------
    float S[16][4];
#pragma unroll
    for (int i = 0; i < 16; i++)
#pragma unroll
        for (int e = 0; e < 4; e++) S[i][e] = 0.f;

#pragma unroll
    for (int ks = 0; ks < 4; ks++) {
        uint32_t qh[4], ql[4];
        const uint32_t aoff = (uint32_t)(((ks * 2 + khA) ^ swA) << 4);
        ldsm4(qh, aQhi + aoff);
        ldsm4(ql, aQlo + aoff);
        const uint32_t boff = (uint32_t)(((ks * 2 + khB) ^ swB) << 4);
#pragma unroll
        for (int g = 0; g < 8; g++) {
            if (g > rb) break;
            uint32_t kh[4], kl[4];
            const uint32_t bb = smb + 32768 + (uint32_t)((g * 16 + rB) * 128);
            ldsm4(kh, bb + boff);
            ldsm4(kl, bb + 16384 + boff);
            mma16816(S[2 * g],     qh, &kh[0]);
            mma16816(S[2 * g],     qh, &kl[0]);
            mma16816(S[2 * g],     ql, &kh[0]);
            mma16816(S[2 * g + 1], qh, &kh[2]);
            mma16816(S[2 * g + 1], qh, &kl[2]);
            mma16816(S[2 * g + 1], ql, &kh[2]);
        }
    }

    // ---------------- softmax (no max-subtract; scores ~N(0,1)) ----------------
    const int row0 = rb * 16 + (lane >> 2);
    const int row1 = row0 + 8;
    const int colb = 2 * (lane & 3);
    float sum0 = 0.f, sum1 = 0.f;
#pragma unroll
    for (int nf = 0; nf < 16; nf++) {
        if (nf > 2 * rb + 1) break;
        const int c0 = nf * 8 + colb, c1 = c0 + 1;
        float e00 = (c0 <= row0) ? __expf(S[nf][0] * 0.125f) : 0.f;
        float e01 = (c1 <= row0) ? __expf(S[nf][1] * 0.125f) : 0.f;
        float e10 = (c0 <= row1) ? __expf(S[nf][2] * 0.125f) : 0.f;
        float e11 = (c1 <= row1) ? __expf(S[nf][3] * 0.125f) : 0.f;
        S[nf][0] = e00; S[nf][1] = e01; S[nf][2] = e10; S[nf][3] = e11;
        sum0 += e00 + e01;
        sum1 += e10 + e11;
    }
    sum0 += __shfl_xor_sync(0xFFFFFFFFu, sum0, 1);
    sum0 += __shfl_xor_sync(0xFFFFFFFFu, sum0, 2);
    sum1 += __shfl_xor_sync(0xFFFFFFFFu, sum1, 1);
    sum1 += __shfl_xor_sync(0xFFFFFFFFu, sum1, 2);
    const float inv0 = 1.0f / sum0;
    const float inv1 = 1.0f / sum1;

    // ---------------- O = P @ V (3-split; P hi/lo built from S accs) ----------------
    float O[8][4];
#pragma unroll
    for (int i = 0; i < 8; i++)
#pragma unroll
        for (int e = 0; e < 4; e++) O[i][e] = 0.f;

#pragma unroll
    for (int ks = 0; ks < 8; ks++) {
        if (ks > rb) break;
        uint32_t phi[4], plo[4];
        hilo_pair(S[2 * ks][0] * inv0,     S[2 * ks][1] * inv0,     phi[0], plo[0]);
        hilo_pair(S[2 * ks][2] * inv1,     S[2 * ks][3] * inv1,     phi[1], plo[1]);
        hilo_pair(S[2 * ks + 1][0] * inv0, S[2 * ks + 1][1] * inv0, phi[2], plo[2]);
        hilo_pair(S[2 * ks + 1][2] * inv1, S[2 * ks + 1][3] * inv1, phi[3], plo[3]);

        const uint32_t vbase = smb + 65536 + (uint32_t)((ks >> 2) * 16384);
        const uint32_t boff = (uint32_t)((((ks & 3) * 2 + khB) ^ swB) << 4);
#pragma unroll
        for (int g = 0; g < 4; g++) {
            uint32_t vh[4], vl[4];
            const uint32_t bb = vbase + (uint32_t)((g * 16 + rB) * 128);
            ldsm4(vh, bb + boff);
            ldsm4(vl, bb + 8192 + boff);
            mma16816(O[2 * g],     phi, &vh[0]);
            mma16816(O[2 * g],     phi, &vl[0]);
            mma16816(O[2 * g],     plo, &vh[0]);
            mma16816(O[2 * g + 1], phi, &vh[2]);
            mma16816(O[2 * g + 1], phi, &vl[2]);
            mma16816(O[2 * g + 1], plo, &vh[2]);
        }
    }

    // ---------------- epilogue: att bf16 hi/lo [b][t][h*64+d] ----------------
    const size_t obase = (size_t)b * T * HD + h * D;
#pragma unroll
    for (int nf = 0; nf < 8; nf++) {
        const int d0 = nf * 8 + colb;
        uint32_t hi, lo;
        hilo_pair(O[nf][0], O[nf][1], hi, lo);
        *(uint32_t*)(g_atthi + obase + (size_t)row0 * HD + d0) = hi;
        *(uint32_t*)(g_attlo + obase + (size_t)row0 * HD + d0) = lo;
        hilo_pair(O[nf][2], O[nf][3], hi, lo);
        *(uint32_t*)(g_atthi + obase + (size_t)row1 * HD + d0) = hi;
        *(uint32_t*)(g_attlo + obase + (size_t)row1 * HD + d0) = lo;
    }
}

// =================================================================================
extern "C" void kernel_launch(void* const* d_in, const int* in_sizes, int n_in,
                              void* d_out, int out_size)
{
    (void)in_sizes; (void)n_in; (void)out_size;
    const float* x  = (const float*)d_in[0];
    const float* Wq = (const float*)d_in[1];
    const float* Wk = (const float*)d_in[2];
    const float* Wv = (const float*)d_in[3];
    const float* Wp = (const float*)d_in[4];
    const float* bp = (const float*)d_in[5];
    float* out = (float*)d_out;

    cudaFuncSetAttribute(mma_gemm<false>, cudaFuncAttributeMaxDynamicSharedMemorySize, MMA_SMEM);
    cudaFuncSetAttribute(mma_gemm<true>,  cudaFuncAttributeMaxDynamicSharedMemorySize, MMA_SMEM);
    cudaFuncSetAttribute(attn_mma, cudaFuncAttributeMaxDynamicSharedMemorySize, ATTN_SMEM);

    conv_x_kernel<<<(BATCH * T * C / 4) / 256, 256>>>(x);
    conv_w_kernel<<<(NQKV * C + 255) / 256, 256>>>(Wq, Wk, Wv);
    conv_wp_kernel<<<(HD * C + 255) / 256, 256>>>(Wp);

    mma_gemm<false><<<dim3(BATCH, 9), 256, MMA_SMEM>>>(nullptr, nullptr);
    attn_mma<<<dim3(BATCH, H), 256, ATTN_SMEM>>>();
    mma_gemm<true><<<dim3(BATCH, 3), 256, MMA_SMEM>>>(bp, out);
}

// round 5
// speedup vs baseline: 2.9615x; 1.0524x over previous
#include <cuda_runtime.h>
#include <cuda_bf16.h>
#include <cstdint>

#define BATCH 512
#define T 128
#define C 384
#define H 6
#define D 64
#define HD 384
#define NQKV 1152

typedef unsigned long long ull;

// ---------------- scratch (device globals; no runtime allocation) ----------------
__device__ __align__(256) __nv_bfloat16 g_xhi[(size_t)BATCH * T * C];
__device__ __align__(256) __nv_bfloat16 g_xlo[(size_t)BATCH * T * C];
__device__ __align__(256) __nv_bfloat16 g_wthi[(size_t)NQKV * C];   // [n][k]
__device__ __align__(256) __nv_bfloat16 g_wtlo[(size_t)NQKV * C];
__device__ __align__(256) __nv_bfloat16 g_wpthi[(size_t)HD * C];    // [n][k] = Wp[k][n]
__device__ __align__(256) __nv_bfloat16 g_wptlo[(size_t)HD * C];
// q,k,v all [b][h][t][d] hi/lo
__device__ __align__(256) __nv_bfloat16 g_qhi[(size_t)BATCH * H * T * D];
__device__ __align__(256) __nv_bfloat16 g_qlo[(size_t)BATCH * H * T * D];
__device__ __align__(256) __nv_bfloat16 g_khi[(size_t)BATCH * H * T * D];
__device__ __align__(256) __nv_bfloat16 g_klo[(size_t)BATCH * H * T * D];
__device__ __align__(256) __nv_bfloat16 g_vhi[(size_t)BATCH * H * T * D];
__device__ __align__(256) __nv_bfloat16 g_vlo[(size_t)BATCH * H * T * D];
__device__ __align__(256) __nv_bfloat16 g_atthi[(size_t)BATCH * T * HD];
__device__ __align__(256) __nv_bfloat16 g_attlo[(size_t)BATCH * T * HD];

// ---------------- helpers (baseline PTX, compute_103-safe) ----------------
__device__ __forceinline__ uint32_t smem_u32(const void* p) {
    uint32_t a;
    asm("{ .reg .u64 t; cvta.to.shared.u64 t, %1; cvt.u32.u64 %0, t; }" : "=r"(a) : "l"(p));
    return a;
}
__device__ __forceinline__ void ldsm4(uint32_t* r, uint32_t addr) {
    asm volatile("ldmatrix.sync.aligned.m8n8.x4.shared.b16 {%0,%1,%2,%3}, [%4];"
        : "=r"(r[0]), "=r"(r[1]), "=r"(r[2]), "=r"(r[3]) : "r"(addr));
}
__device__ __forceinline__ void ldsm4t(uint32_t* r, uint32_t addr) {
    asm volatile("ldmatrix.sync.aligned.m8n8.x4.trans.shared.b16 {%0,%1,%2,%3}, [%4];"
        : "=r"(r[0]), "=r"(r[1]), "=r"(r[2]), "=r"(r[3]) : "r"(addr));
}
__device__ __forceinline__ void mma16816(float* c, const uint32_t* a, const uint32_t* b) {
    asm volatile("mma.sync.aligned.m16n8k16.row.col.f32.bf16.bf16.f32 "
        "{%0,%1,%2,%3}, {%4,%5,%6,%7}, {%8,%9}, {%0,%1,%2,%3};"
        : "+f"(c[0]), "+f"(c[1]), "+f"(c[2]), "+f"(c[3])
        : "r"(a[0]), "r"(a[1]), "r"(a[2]), "r"(a[3]), "r"(b[0]), "r"(b[1]));
}
__device__ __forceinline__ void cpa16(uint32_t dst, const void* src) {
    asm volatile("cp.async.cg.shared.global [%0], [%1], 16;" :: "r"(dst), "l"(src));
}
#define CPA_COMMIT() asm volatile("cp.async.commit_group;" ::: "memory")
#define CPA_WAIT1()  asm volatile("cp.async.wait_group 1;" ::: "memory")
#define CPA_WAIT0()  asm volatile("cp.async.wait_group 0;" ::: "memory")

__device__ __forceinline__ uint32_t cvt_bf16x2(float lo, float hi) {
    uint32_t r;
    asm("cvt.rn.bf16x2.f32 %0, %1, %2;" : "=r"(r) : "f"(hi), "f"(lo));
    return r;
}
__device__ __forceinline__ float lo_f(uint32_t u) { return __uint_as_float(u << 16); }
__device__ __forceinline__ float hi_f(uint32_t u) { return __uint_as_float(u & 0xFFFF0000u); }
__device__ __forceinline__ void hilo_pair(float a, float b, uint32_t& h, uint32_t& l) {
    h = cvt_bf16x2(a, b);
    l = cvt_bf16x2(a - lo_f(h), b - hi_f(h));
}

// =================================================================================
// Conversion kernels (fp32 -> bf16 hi/lo split)
// =================================================================================
__global__ void conv_x_kernel(const float* __restrict__ x) {
    size_t i = ((size_t)blockIdx.x * 256 + threadIdx.x) * 4;
    float4 v = *(const float4*)(x + i);
    uint32_t h0, l0, h1, l1;
    hilo_pair(v.x, v.y, h0, l0);
    hilo_pair(v.z, v.w, h1, l1);
    *(uint32_t*)(g_xhi + i)     = h0;
    *(uint32_t*)(g_xhi + i + 2) = h1;
    *(uint32_t*)(g_xlo + i)     = l0;
    *(uint32_t*)(g_xlo + i + 2) = l1;
}

__global__ void conv_w_kernel(const float* __restrict__ Wq, const float* __restrict__ Wk,
                              const float* __restrict__ Wv) {
    int idx = blockIdx.x * 256 + threadIdx.x;   // n*C + k
    if (idx >= NQKV * C) return;
    int n = idx / C, k = idx - n * C;
    int which = n / HD, rem = n - which * HD;
    int h = rem >> 6, d = rem & 63;
    const float* W = (which == 0) ? Wq : (which == 1) ? Wk : Wv;
    float v = W[((size_t)h * C + k) * D + d];
    __nv_bfloat16 hi = __float2bfloat16(v);
    g_wthi[idx] = hi;
    g_wtlo[idx] = __float2bfloat16(v - __bfloat162float(hi));
}

__global__ void conv_wp_kernel(const float* __restrict__ Wp) {
    int idx = blockIdx.x * 256 + threadIdx.x;   // n*C + k
    if (idx >= HD * C) return;
    int n = idx / C, k = idx - n * C;
    float v = Wp[(size_t)k * C + n];
    __nv_bfloat16 hi = __float2bfloat16(v);
    g_wpthi[idx] = hi;
    g_wptlo[idx] = __float2bfloat16(v - __bfloat162float(hi));
}

// =================================================================================
// Tensor-core GEMM: Y[128 x 64] = A[128 x 384] @ B[n][k]^T, bf16 3-split.
// CTA tile 128x64, 2 CTAs/SM. Grid (ntiles, batch) so consecutive CTAs share A in L2.
// Stage (48KB): Ahi@0, Alo@16K, Bhi@32K, Blo@40K; double-buffered = 96KB.
// 8 warps as 4(m) x 2(n); warp tile 32x32.
// PROJ=false: blockIdx.x -> (which, head); epilogue writes q/k/v bf16 hi/lo [t][d].
// PROJ=true : epilogue adds bias, writes fp32 out.
// =================================================================================
#define STAGE_BYTES 49152
#define GEMM_SMEM (2 * STAGE_BYTES)

template <bool PROJ>
__global__ __launch_bounds__(256, 2)
void mma_gemm(const float* __restrict__ bp, float* __restrict__ out)
{
    extern __shared__ __align__(1024) char sm[];
    const uint32_t smb = smem_u32(sm);
    const int tid = threadIdx.x, wid = tid >> 5, lane = tid & 31;
    const int b = blockIdx.y, n0 = blockIdx.x * 64;
    const int wm = (wid >> 1) * 32;     // 0,32,64,96
    const int wn = (wid & 1) * 32;      // 0,32

    const __nv_bfloat16* __restrict__ Ahi = (PROJ ? g_atthi : g_xhi) + (size_t)b * T * C;
    const __nv_bfloat16* __restrict__ Alo = (PROJ ? g_attlo : g_xlo) + (size_t)b * T * C;
    const __nv_bfloat16* __restrict__ Bhi = (PROJ ? g_wpthi : g_wthi) + (size_t)n0 * C;
    const __nv_bfloat16* __restrict__ Blo = (PROJ ? g_wptlo : g_wtlo) + (size_t)n0 * C;

    const int l_row = tid >> 3;          // 0..31
    const int l_seg = tid & 7;

    auto load_chunk = [&](int c, int s) {
        const int c0 = c * 64;
        const uint32_t sb = smb + s * STAGE_BYTES;
#pragma unroll
        for (int p = 0; p < 4; p++) {
            const int row = l_row + p * 32;
            const uint32_t doff = (uint32_t)(row * 128 + ((l_seg ^ (row & 7)) << 4));
            const size_t soff = (size_t)row * C + c0 + l_seg * 8;
            cpa16(sb + doff,         Ahi + soff);
            cpa16(sb + 16384 + doff, Alo + soff);
        }
#pragma unroll
        for (int p = 0; p < 2; p++) {
            const int row = l_row + p * 32;   // 0..63
            const uint32_t doff = (uint32_t)(row * 128 + ((l_seg ^ (row & 7)) << 4));
            const size_t soff = (size_t)row * C + c0 + l_seg * 8;
            cpa16(sb + 32768 + doff, Bhi + soff);
            cpa16(sb + 40960 + doff, Blo + soff);
        }
        CPA_COMMIT();
    };

    float acc[2][4][4];
#pragma unroll
    for (int i = 0; i < 2; i++)
#pragma unroll
        for (int j = 0; j < 4; j++)
#pragma unroll
            for (int e = 0; e < 4; e++) acc[i][j][e] = 0.f;

    const int rA  = (lane & 7) + ((lane >> 3) & 1) * 8;
    const int khA = lane >> 4;
    const int swA = rA & 7;
    const int rB  = (lane & 7) + (lane >> 4) * 8;
    const int khB = (lane >> 3) & 1;
    const int swB = rB & 7;

    load_chunk(0, 0);
    load_chunk(1, 1);

    for (int c = 0; c < 6; c++) {
        if (c == 5) CPA_WAIT0(); else CPA_WAIT1();
        __syncthreads();

        const uint32_t sb = smb + (c & 1) * STAGE_BYTES;
        const uint32_t aBase = sb + (uint32_t)((wm + rA) * 128);
        const uint32_t bBase = sb + 32768 + (uint32_t)((wn + rB) * 128);

#pragma unroll
        for (int ks = 0; ks < 4; ks++) {
            const uint32_t aoff = (uint32_t)(((ks * 2 + khA) ^ swA) << 4);
            const uint32_t boff = (uint32_t)(((ks * 2 + khB) ^ swB) << 4);
            uint32_t ahi[2][4], alo[2][4], bh[2][4], bl[2][4];
#pragma unroll
            for (int mf = 0; mf < 2; mf++) {
                ldsm4(ahi[mf], aBase + mf * 2048 + aoff);
                ldsm4(alo[mf], aBase + 16384 + mf * 2048 + aoff);
            }
#pragma unroll
            for (int g = 0; g < 2; g++) {
                ldsm4(bh[g], bBase + g * 2048 + boff);
                ldsm4(bl[g], bBase + 8192 + g * 2048 + boff);
            }
#pragma unroll
            for (int mf = 0; mf < 2; mf++) {
#pragma unroll
                for (int nf = 0; nf < 4; nf++) {
                    const uint32_t* bhf = &bh[nf >> 1][(nf & 1) * 2];
                    const uint32_t* blf = &bl[nf >> 1][(nf & 1) * 2];
                    mma16816(acc[mf][nf], ahi[mf], bhf);
                    mma16816(acc[mf][nf], ahi[mf], blf);
                    mma16816(acc[mf][nf], alo[mf], bhf);
                }
            }
        }
        __syncthreads();
        if (c + 2 < 6) load_chunk(c + 2, (c & 1));
    }

    // ---------------- epilogue ----------------
    const int qrow = lane >> 2;
    const int qcol = (lane & 3) * 2;

    if (PROJ) {
#pragma unroll
        for (int mf = 0; mf < 2; mf++) {
#pragma unroll
            for (int nf = 0; nf < 4; nf++) {
                const int row = wm + mf * 16 + qrow;
                const int col = n0 + wn + nf * 8 + qcol;
                const float2 bb = *(const float2*)(bp + col);
                float* p0 = out + ((size_t)b * T + row) * HD + col;
                float* p1 = out + ((size_t)b * T + row + 8) * HD + col;
                *(float2*)p0 = make_float2(acc[mf][nf][0] + bb.x, acc[mf][nf][1] + bb.y);
                *(float2*)p1 = make_float2(acc[mf][nf][2] + bb.x, acc[mf][nf][3] + bb.y);
            }
        }
    } else {
        const int which = blockIdx.x / 6;       // 0=q,1=k,2=v
        const int hh = blockIdx.x % 6;
        __nv_bfloat16* bh_ = (which == 0) ? g_qhi : (which == 1) ? g_khi : g_vhi;
        __nv_bfloat16* bl_ = (which == 0) ? g_qlo : (which == 1) ? g_klo : g_vlo;
        const size_t hb = ((size_t)(b * H + hh) * T) * D;
#pragma unroll
        for (int mf = 0; mf < 2; mf++) {
#pragma unroll
            for (int nf = 0; nf < 4; nf++) {
                const int row = wm + mf * 16 + qrow;
                const int dd = wn + nf * 8 + qcol;
                const size_t o0 = hb + (size_t)row * D + dd;
                uint32_t hi, lo;
                hilo_pair(acc[mf][nf][0], acc[mf][nf][1], hi, lo);
                *(uint32_t*)(bh_ + o0) = hi;
                *(uint32_t*)(bl_ + o0) = lo;
                hilo_pair(acc[mf][nf][2], acc[mf][nf][3], hi, lo);
                *(uint32_t*)(bh_ + o0 + 8 * D) = hi;
                *(uint32_t*)(bl_ + o0 + 8 * D) = lo;
            }
        }
    }
}

// =================================================================================
// MMA attention per (b, h). 8 warps; warp owns 16 query rows (block rb, remapped).
// S = Q@K^T 3-split -> softmax -> P hi/lo in regs -> O = P@V 3-split where V is
// stored [t][d] and B-fragments come from ldmatrix.trans. Causal block-skip.
// smem: qhi 0, qlo 16K, khi 32K, klo 48K, vhi 64K, vlo 80K  (96KB total)
// =================================================================================
#define ATTN_SMEM 98304

__global__ __launch_bounds__(256, 1)
void attn_mma()
{
    extern __shared__ __align__(1024) char sm[];
    const uint32_t smb = smem_u32(sm);
    const int tid = threadIdx.x, w = tid >> 5, lane = tid & 31;
    const int b = blockIdx.x, h = blockIdx.y;
    const int rb = (w < 4) ? w : (11 - w);     // row-block; SMSP pairs balanced

    const size_t blk = (size_t)(b * H + h) * (T * D);
    {
        const int seg = tid & 7;
#pragma unroll
        for (int p = 0; p < 4; p++) {
            const int row = (tid + p * 256) >> 3;          // 0..127
            const uint32_t doff = (uint32_t)(row * 128 + ((seg ^ (row & 7)) << 4));
            const size_t soff = blk + (size_t)row * D + seg * 8;
            cpa16(smb + doff,         g_qhi + soff);
            cpa16(smb + 16384 + doff, g_qlo + soff);
            cpa16(smb + 32768 + doff, g_khi + soff);
            cpa16(smb + 49152 + doff, g_klo + soff);
            cpa16(smb + 65536 + doff, g_vhi + soff);
            cpa16(smb + 81920 + doff, g_vlo + soff);
        }
    }
    CPA_COMMIT();
    CPA_WAIT0();
    __syncthreads();

    const int rA  = (lane & 7) + ((lane >> 3) & 1) * 8;
    const int khA = lane >> 4;
    const int swA = rA & 7;
    const int rB  = (lane & 7) + (lane >> 4) * 8;
    const int khB = (lane >> 3) & 1;
    const int swB = rB & 7;

    const uint32_t aQhi = smb + (uint32_t)((rb * 16 + rA) * 128);
    const uint32_t aQlo = aQhi + 16384;

    // ---------------- S = Q @ K^T (3-split, causal block-skip) ----------------
    float S[16][4];
#pragma unroll
    for (int i = 0; i < 16; i++)
#pragma unroll
        for (int e = 0; e < 4; e++) S[i][e] = 0.f;

#pragma unroll
    for (int ks = 0; ks < 4; ks++) {
        uint32_t qh[4], ql[4];
        const uint32_t aoff = (uint32_t)(((ks * 2 + khA) ^ swA) << 4);
        ldsm4(qh, aQhi + aoff);
        ldsm4(ql, aQlo + aoff);
        const uint32_t boff = (uint32_t)(((ks * 2 + khB) ^ swB) << 4);
#pragma unroll
        for (int g = 0; g < 8; g++) {
            if (g > rb) break;
            uint32_t kh[4], kl[4];
            const uint32_t bb = smb + 32768 + (uint32_t)((g * 16 + rB) * 128);
            ldsm4(kh, bb + boff);
            ldsm4(kl, bb + 16384 + boff);
            mma16816(S[2 * g],     qh, &kh[0]);
            mma16816(S[2 * g],     qh, &kl[0]);
            mma16816(S[2 * g],     ql, &kh[0]);
            mma16816(S[2 * g + 1], qh, &kh[2]);
            mma16816(S[2 * g + 1], qh, &kl[2]);
            mma16816(S[2 * g + 1], ql, &kh[2]);
        }
    }

    // ---------------- softmax (no max-subtract; scores ~N(0,1)) ----------------
    const int row0 = rb * 16 + (lane >> 2);
    const int row1 = row0 + 8;
    const int colb = 2 * (lane & 3);
    float sum0 = 0.f, sum1 = 0.f;
#pragma unroll
    for (int nf = 0; nf < 16; nf++) {
        if (nf > 2 * rb + 1) break;
        const int c0 = nf * 8 + colb, c1 = c0 + 1;
        float e00 = (c0 <= row0) ? __expf(S[nf][0] * 0.125f) : 0.f;
        float e01 = (c1 <= row0) ? __expf(S[nf][1] * 0.125f) : 0.f;
        float e10 = (c0 <= row1) ? __expf(S[nf][2] * 0.125f) : 0.f;
        float e11 = (c1 <= row1) ? __expf(S[nf][3] * 0.125f) : 0.f;
        S[nf][0] = e00; S[nf][1] = e01; S[nf][2] = e10; S[nf][3] = e11;
        sum0 += e00 + e01;
        sum1 += e10 + e11;
    }
    sum0 += __shfl_xor_sync(0xFFFFFFFFu, sum0, 1);
    sum0 += __shfl_xor_sync(0xFFFFFFFFu, sum0, 2);
    sum1 += __shfl_xor_sync(0xFFFFFFFFu, sum1, 1);
    sum1 += __shfl_xor_sync(0xFFFFFFFFu, sum1, 2);
    const float inv0 = 1.0f / sum0;
    const float inv1 = 1.0f / sum1;

    // ---------------- O = P @ V (3-split; V via ldmatrix.trans on [t][d]) --------
    float O[8][4];
#pragma unroll
    for (int i = 0; i < 8; i++)
#pragma unroll
        for (int e = 0; e < 4; e++) O[i][e] = 0.f;

    // trans-ldsm lane geometry: matrix m = lane>>3, row r = lane&7
    const int mT = lane >> 3;
    const int rT = lane & 7;

#pragma unroll
    for (int ks = 0; ks < 8; ks++) {
        if (ks > rb) break;
        uint32_t phi[4], plo[4];
        hilo_pair(S[2 * ks][0] * inv0,     S[2 * ks][1] * inv0,     phi[0], plo[0]);
        hilo_pair(S[2 * ks][2] * inv1,     S[2 * ks][3] * inv1,     phi[1], plo[1]);
        hilo_pair(S[2 * ks + 1][0] * inv0, S[2 * ks + 1][1] * inv0, phi[2], plo[2]);
        hilo_pair(S[2 * ks + 1][2] * inv1, S[2 * ks + 1][3] * inv1, phi[3], plo[3]);

        const int srow = ks * 16 + (mT & 1) * 8 + rT;
        const uint32_t rowOff = (uint32_t)(srow * 128);
#pragma unroll
        for (int g = 0; g < 4; g++) {
            const int dseg = g * 2 + (mT >> 1);
            const uint32_t addr = rowOff + (uint32_t)(((dseg ^ (srow & 7)) << 4));
            uint32_t vh[4], vl[4];
            ldsm4t(vh, smb + 65536 + addr);
            ldsm4t(vl, smb + 81920 + addr);
            mma16816(O[2 * g],     phi, &vh[0]);
            mma16816(O[2 * g],     phi, &vl[0]);
            mma16816(O[2 * g],     plo, &vh[0]);
            mma16816(O[2 * g + 1], phi, &vh[2]);
            mma16816(O[2 * g + 1], phi, &vl[2]);
            mma16816(O[2 * g + 1], plo, &vh[2]);
        }
    }

    // ---------------- epilogue: att bf16 hi/lo [b][t][h*64+d] ----------------
    const size_t obase = (size_t)b * T * HD + h * D;
#pragma unroll
    for (int nf = 0; nf < 8; nf++) {
        const int d0 = nf * 8 + colb;
        uint32_t hi, lo;
        hilo_pair(O[nf][0], O[nf][1], hi, lo);
        *(uint32_t*)(g_atthi + obase + (size_t)row0 * HD + d0) = hi;
        *(uint32_t*)(g_attlo + obase + (size_t)row0 * HD + d0) = lo;
        hilo_pair(O[nf][2], O[nf][3], hi, lo);
        *(uint32_t*)(g_atthi + obase + (size_t)row1 * HD + d0) = hi;
        *(uint32_t*)(g_attlo + obase + (size_t)row1 * HD + d0) = lo;
    }
}

// =================================================================================
extern "C" void kernel_launch(void* const* d_in, const int* in_sizes, int n_in,
                              void* d_out, int out_size)
{
    (void)in_sizes; (void)n_in; (void)out_size;
    const float* x  = (const float*)d_in[0];
    const float* Wq = (const float*)d_in[1];
    const float* Wk = (const float*)d_in[2];
    const float* Wv = (const float*)d_in[3];
    const float* Wp = (const float*)d_in[4];
    const float* bp = (const float*)d_in[5];
    float* out = (float*)d_out;

    cudaFuncSetAttribute(mma_gemm<false>, cudaFuncAttributeMaxDynamicSharedMemorySize, GEMM_SMEM);
    cudaFuncSetAttribute(mma_gemm<true>,  cudaFuncAttributeMaxDynamicSharedMemorySize, GEMM_SMEM);
    cudaFuncSetAttribute(attn_mma, cudaFuncAttributeMaxDynamicSharedMemorySize, ATTN_SMEM);

    conv_x_kernel<<<(BATCH * T * C / 4) / 256, 256>>>(x);
    conv_w_kernel<<<(NQKV * C + 255) / 256, 256>>>(Wq, Wk, Wv);
    conv_wp_kernel<<<(HD * C + 255) / 256, 256>>>(Wp);

    mma_gemm<false><<<dim3(18, BATCH), 256, GEMM_SMEM>>>(nullptr, nullptr);
    attn_mma<<<dim3(BATCH, H), 256, ATTN_SMEM>>>();
    mma_gemm<true><<<dim3(6, BATCH), 256, GEMM_SMEM>>>(bp, out);
}

// round 6
// speedup vs baseline: 2.9866x; 1.0085x over previous
#include <cuda_runtime.h>
#include <cuda_bf16.h>
#include <cstdint>

#define BATCH 512
#define T 128
#define C 384
#define H 6
#define D 64
#define HD 384
#define NQKV 1152

typedef unsigned long long ull;

// ---------------- scratch (device globals; no runtime allocation) ----------------
__device__ __align__(256) __nv_bfloat16 g_xhi[(size_t)BATCH * T * C];
__device__ __align__(256) __nv_bfloat16 g_xlo[(size_t)BATCH * T * C];
__device__ __align__(256) __nv_bfloat16 g_wthi[(size_t)NQKV * C];   // [n][k]
__device__ __align__(256) __nv_bfloat16 g_wtlo[(size_t)NQKV * C];
__device__ __align__(256) __nv_bfloat16 g_wpthi[(size_t)HD * C];    // [n][k] = Wp[k][n]
__device__ __align__(256) __nv_bfloat16 g_wptlo[(size_t)HD * C];
// q,k,v all [b][h][t][d] hi/lo
__device__ __align__(256) __nv_bfloat16 g_qhi[(size_t)BATCH * H * T * D];
__device__ __align__(256) __nv_bfloat16 g_qlo[(size_t)BATCH * H * T * D];
__device__ __align__(256) __nv_bfloat16 g_khi[(size_t)BATCH * H * T * D];
__device__ __align__(256) __nv_bfloat16 g_klo[(size_t)BATCH * H * T * D];
__device__ __align__(256) __nv_bfloat16 g_vhi[(size_t)BATCH * H * T * D];
__device__ __align__(256) __nv_bfloat16 g_vlo[(size_t)BATCH * H * T * D];
__device__ __align__(256) __nv_bfloat16 g_atthi[(size_t)BATCH * T * HD];
__device__ __align__(256) __nv_bfloat16 g_attlo[(size_t)BATCH * T * HD];

// ---------------- helpers (baseline PTX, compute_103-safe) ----------------
__device__ __forceinline__ uint32_t smem_u32(const void* p) {
    uint32_t a;
    asm("{ .reg .u64 t; cvta.to.shared.u64 t, %1; cvt.u32.u64 %0, t; }" : "=r"(a) : "l"(p));
    return a;
}
__device__ __forceinline__ void ldsm4(uint32_t* r, uint32_t addr) {
    asm volatile("ldmatrix.sync.aligned.m8n8.x4.shared.b16 {%0,%1,%2,%3}, [%4];"
        : "=r"(r[0]), "=r"(r[1]), "=r"(r[2]), "=r"(r[3]) : "r"(addr));
}
__device__ __forceinline__ void ldsm4t(uint32_t* r, uint32_t addr) {
    asm volatile("ldmatrix.sync.aligned.m8n8.x4.trans.shared.b16 {%0,%1,%2,%3}, [%4];"
        : "=r"(r[0]), "=r"(r[1]), "=r"(r[2]), "=r"(r[3]) : "r"(addr));
}
__device__ __forceinline__ void mma16816(float* c, const uint32_t* a, const uint32_t* b) {
    asm volatile("mma.sync.aligned.m16n8k16.row.col.f32.bf16.bf16.f32 "
        "{%0,%1,%2,%3}, {%4,%5,%6,%7}, {%8,%9}, {%0,%1,%2,%3};"
        : "+f"(c[0]), "+f"(c[1]), "+f"(c[2]), "+f"(c[3])
        : "r"(a[0]), "r"(a[1]), "r"(a[2]), "r"(a[3]), "r"(b[0]), "r"(b[1]));
}
__device__ __forceinline__ void cpa16(uint32_t dst, const void* src) {
    asm volatile("cp.async.cg.shared.global [%0], [%1], 16;" :: "r"(dst), "l"(src));
}
#define CPA_COMMIT() asm volatile("cp.async.commit_group;" ::: "memory")
#define CPA_WAIT1()  asm volatile("cp.async.wait_group 1;" ::: "memory")
#define CPA_WAIT0()  asm volatile("cp.async.wait_group 0;" ::: "memory")

__device__ __forceinline__ uint32_t cvt_bf16x2(float lo, float hi) {
    uint32_t r;
    asm("cvt.rn.bf16x2.f32 %0, %1, %2;" : "=r"(r) : "f"(hi), "f"(lo));
    return r;
}
__device__ __forceinline__ float lo_f(uint32_t u) { return __uint_as_float(u << 16); }
__device__ __forceinline__ float hi_f(uint32_t u) { return __uint_as_float(u & 0xFFFF0000u); }
__device__ __forceinline__ void hilo_pair(float a, float b, uint32_t& h, uint32_t& l) {
    h = cvt_bf16x2(a, b);
    l = cvt_bf16x2(a - lo_f(h), b - hi_f(h));
}

// =================================================================================
// Conversion kernels (fp32 -> bf16 hi/lo split)
// =================================================================================
__global__ void conv_x_kernel(const float* __restrict__ x) {
    size_t i = ((size_t)blockIdx.x * 256 + threadIdx.x) * 4;
    float4 v = *(const float4*)(x + i);
    uint32_t h0, l0, h1, l1;
    hilo_pair(v.x, v.y, h0, l0);
    hilo_pair(v.z, v.w, h1, l1);
    *(uint32_t*)(g_xhi + i)     = h0;
    *(uint32_t*)(g_xhi + i + 2) = h1;
    *(uint32_t*)(g_xlo + i)     = l0;
    *(uint32_t*)(g_xlo + i + 2) = l1;
}

__global__ void conv_w_kernel(const float* __restrict__ Wq, const float* __restrict__ Wk,
                              const float* __restrict__ Wv) {
    int idx = blockIdx.x * 256 + threadIdx.x;   // n*C + k
    if (idx >= NQKV * C) return;
    int n = idx / C, k = idx - n * C;
    int which = n / HD, rem = n - which * HD;
    int h = rem >> 6, d = rem & 63;
    const float* W = (which == 0) ? Wq : (which == 1) ? Wk : Wv;
    float v = W[((size_t)h * C + k) * D + d];
    __nv_bfloat16 hi = __float2bfloat16(v);
    g_wthi[idx] = hi;
    g_wtlo[idx] = __float2bfloat16(v - __bfloat162float(hi));
}

__global__ void conv_wp_kernel(const float* __restrict__ Wp) {
    int idx = blockIdx.x * 256 + threadIdx.x;   // n*C + k
    if (idx >= HD * C) return;
    int n = idx / C, k = idx - n * C;
    float v = Wp[(size_t)k * C + n];
    __nv_bfloat16 hi = __float2bfloat16(v);
    g_wpthi[idx] = hi;
    g_wptlo[idx] = __float2bfloat16(v - __bfloat162float(hi));
}

// =================================================================================
// Tensor-core GEMM: Y[128 x 64] = A[128 x 384] @ B[n][k]^T, bf16 3-split.
// 3-pass MMA order (hi.hi / hi.lo / lo.hi) => same-acc dependency distance 8.
// =================================================================================
#define STAGE_BYTES 49152
#define GEMM_SMEM (2 * STAGE_BYTES)

template <bool PROJ>
__global__ __launch_bounds__(256, 2)
void mma_gemm(const float* __restrict__ bp, float* __restrict__ out)
{
    extern __shared__ __align__(1024) char sm[];
    const uint32_t smb = smem_u32(sm);
    const int tid = threadIdx.x, wid = tid >> 5, lane = tid & 31;
    const int b = blockIdx.y, n0 = blockIdx.x * 64;
    const int wm = (wid >> 1) * 32;     // 0,32,64,96
    const int wn = (wid & 1) * 32;      // 0,32

    const __nv_bfloat16* __restrict__ Ahi = (PROJ ? g_atthi : g_xhi) + (size_t)b * T * C;
    const __nv_bfloat16* __restrict__ Alo = (PROJ ? g_attlo : g_xlo) + (size_t)b * T * C;
    const __nv_bfloat16* __restrict__ Bhi = (PROJ ? g_wpthi : g_wthi) + (size_t)n0 * C;
    const __nv_bfloat16* __restrict__ Blo = (PROJ ? g_wptlo : g_wtlo) + (size_t)n0 * C;

    const int l_row = tid >> 3;          // 0..31
    const int l_seg = tid & 7;

    auto load_chunk = [&](int c, int s) {
        const int c0 = c * 64;
        const uint32_t sb = smb + s * STAGE_BYTES;
#pragma unroll
        for (int p = 0; p < 4; p++) {
            const int row = l_row + p * 32;
            const uint32_t doff = (uint32_t)(row * 128 + ((l_seg ^ (row & 7)) << 4));
            const size_t soff = (size_t)row * C + c0 + l_seg * 8;
            cpa16(sb + doff,         Ahi + soff);
            cpa16(sb + 16384 + doff, Alo + soff);
        }
#pragma unroll
        for (int p = 0; p < 2; p++) {
            const int row = l_row + p * 32;   // 0..63
            const uint32_t doff = (uint32_t)(row * 128 + ((l_seg ^ (row & 7)) << 4));
            const size_t soff = (size_t)row * C + c0 + l_seg * 8;
            cpa16(sb + 32768 + doff, Bhi + soff);
            cpa16(sb + 40960 + doff, Blo + soff);
        }
        CPA_COMMIT();
    };

    float acc[2][4][4];
#pragma unroll
    for (int i = 0; i < 2; i++)
#pragma unroll
        for (int j = 0; j < 4; j++)
#pragma unroll
            for (int e = 0; e < 4; e++) acc[i][j][e] = 0.f;

    const int rA  = (lane & 7) + ((lane >> 3) & 1) * 8;
    const int khA = lane >> 4;
    const int swA = rA & 7;
    const int rB  = (lane & 7) + (lane >> 4) * 8;
    const int khB = (lane >> 3) & 1;
    const int swB = rB & 7;

    load_chunk(0, 0);
    load_chunk(1, 1);

    for (int c = 0; c < 6; c++) {
        if (c == 5) CPA_WAIT0(); else CPA_WAIT1();
        __syncthreads();

        const uint32_t sb = smb + (c & 1) * STAGE_BYTES;
        const uint32_t aBase = sb + (uint32_t)((wm + rA) * 128);
        const uint32_t bBase = sb + 32768 + (uint32_t)((wn + rB) * 128);

#pragma unroll
        for (int ks = 0; ks < 4; ks++) {
            const uint32_t aoff = (uint32_t)(((ks * 2 + khA) ^ swA) << 4);
            const uint32_t boff = (uint32_t)(((ks * 2 + khB) ^ swB) << 4);
            uint32_t ahi[2][4], alo[2][4], bh[2][4], bl[2][4];
#pragma unroll
            for (int mf = 0; mf < 2; mf++) {
                ldsm4(ahi[mf], aBase + mf * 2048 + aoff);
                ldsm4(alo[mf], aBase + 16384 + mf * 2048 + aoff);
            }
#pragma unroll
            for (int g = 0; g < 2; g++) {
                ldsm4(bh[g], bBase + g * 2048 + boff);
                ldsm4(bl[g], bBase + 8192 + g * 2048 + boff);
            }
            // pass 1: hi * hi (8 independent accs)
#pragma unroll
            for (int mf = 0; mf < 2; mf++)
#pragma unroll
                for (int nf = 0; nf < 4; nf++)
                    mma16816(acc[mf][nf], ahi[mf], &bh[nf >> 1][(nf & 1) * 2]);
            // pass 2: hi * lo
#pragma unroll
            for (int mf = 0; mf < 2; mf++)
#pragma unroll
                for (int nf = 0; nf < 4; nf++)
                    mma16816(acc[mf][nf], ahi[mf], &bl[nf >> 1][(nf & 1) * 2]);
            // pass 3: lo * hi
#pragma unroll
            for (int mf = 0; mf < 2; mf++)
#pragma unroll
                for (int nf = 0; nf < 4; nf++)
                    mma16816(acc[mf][nf], alo[mf], &bh[nf >> 1][(nf & 1) * 2]);
        }
        __syncthreads();
        if (c + 2 < 6) load_chunk(c + 2, (c & 1));
    }

    // ---------------- epilogue ----------------
    const int qrow = lane >> 2;
    const int qcol = (lane & 3) * 2;

    if (PROJ) {
#pragma unroll
        for (int mf = 0; mf < 2; mf++) {
#pragma unroll
            for (int nf = 0; nf < 4; nf++) {
                const int row = wm + mf * 16 + qrow;
                const int col = n0 + wn + nf * 8 + qcol;
                const float2 bb = *(const float2*)(bp + col);
                float* p0 = out + ((size_t)b * T + row) * HD + col;
                float* p1 = out + ((size_t)b * T + row + 8) * HD + col;
                *(float2*)p0 = make_float2(acc[mf][nf][0] + bb.x, acc[mf][nf][1] + bb.y);
                *(float2*)p1 = make_float2(acc[mf][nf][2] + bb.x, acc[mf][nf][3] + bb.y);
            }
        }
    } else {
        const int which = blockIdx.x / 6;       // 0=q,1=k,2=v
        const int hh = blockIdx.x % 6;
        __nv_bfloat16* bh_ = (which == 0) ? g_qhi : (which == 1) ? g_khi : g_vhi;
        __nv_bfloat16* bl_ = (which == 0) ? g_qlo : (which == 1) ? g_klo : g_vlo;
        const size_t hb = ((size_t)(b * H + hh) * T) * D;
#pragma unroll
        for (int mf = 0; mf < 2; mf++) {
#pragma unroll
            for (int nf = 0; nf < 4; nf++) {
                const int row = wm + mf * 16 + qrow;
                const int dd = wn + nf * 8 + qcol;
                const size_t o0 = hb + (size_t)row * D + dd;
                uint32_t hi, lo;
                hilo_pair(acc[mf][nf][0], acc[mf][nf][1], hi, lo);
                *(uint32_t*)(bh_ + o0) = hi;
                *(uint32_t*)(bl_ + o0) = lo;
                hilo_pair(acc[mf][nf][2], acc[mf][nf][3], hi, lo);
                *(uint32_t*)(bh_ + o0 + 8 * D) = hi;
                *(uint32_t*)(bl_ + o0 + 8 * D) = lo;
            }
        }
    }
}

// =================================================================================
// MMA attention per (b, h). Same structure as R5, MMA chains interleaved.
// =================================================================================
#define ATTN_SMEM 98304

__global__ __launch_bounds__(256, 1)
void attn_mma()
{
    extern __shared__ __align__(1024) char sm[];
    const uint32_t smb = smem_u32(sm);
    const int tid = threadIdx.x, w = tid >> 5, lane = tid & 31;
    const int b = blockIdx.x, h = blockIdx.y;
    const int rb = (w < 4) ? w : (11 - w);     // row-block; SMSP pairs balanced

    const size_t blk = (size_t)(b * H + h) * (T * D);
    {
        const int seg = tid & 7;
#pragma unroll
        for (int p = 0; p < 4; p++) {
            const int row = (tid + p * 256) >> 3;          // 0..127
            const uint32_t doff = (uint32_t)(row * 128 + ((seg ^ (row & 7)) << 4));
            const size_t soff = blk + (size_t)row * D + seg * 8;
            cpa16(smb + doff,         g_qhi + soff);
            cpa16(smb + 16384 + doff, g_qlo + soff);
            cpa16(smb + 32768 + doff, g_khi + soff);
            cpa16(smb + 49152 + doff, g_klo + soff);
            cpa16(smb + 65536 + doff, g_vhi + soff);
            cpa16(smb + 81920 + doff, g_vlo + soff);
        }
    }
    CPA_COMMIT();
    CPA_WAIT0();
    __syncthreads();

    const int rA  = (lane & 7) + ((lane >> 3) & 1) * 8;
    const int khA = lane >> 4;
    const int swA = rA & 7;
    const int rB  = (lane & 7) + (lane >> 4) * 8;
    const int khB = (lane >> 3) & 1;
    const int swB = rB & 7;

    const uint32_t aQhi = smb + (uint32_t)((rb * 16 + rA) * 128);
    const uint32_t aQlo = aQhi + 16384;

    // ---------------- S = Q @ K^T (3-split, causal block-skip) ----------------
    float S[16][4];
#pragma unroll
    for (int i = 0; i < 16; i++)
#pragma unroll
        for (int e = 0; e < 4; e++) S[i][e] = 0.f;

#pragma unroll
    for (int ks = 0; ks < 4; ks++) {
        uint32_t qh[4], ql[4];
        const uint32_t aoff = (uint32_t)(((ks * 2 + khA) ^ swA) << 4);
        ldsm4(qh, aQhi + aoff);
        ldsm4(ql, aQlo + aoff);
        const uint32_t boff = (uint32_t)(((ks * 2 + khB) ^ swB) << 4);
#pragma unroll
        for (int g = 0; g < 8; g += 2) {
            if (g > rb) break;
            uint32_t kh0[4], kl0[4];
            const uint32_t bb0 = smb + 32768 + (uint32_t)((g * 16 + rB) * 128);
            ldsm4(kh0, bb0 + boff);
            ldsm4(kl0, bb0 + 16384 + boff);
            const bool g1ok = (g + 1) <= rb;
            uint32_t kh1[4], kl1[4];
            if (g1ok) {
                const uint32_t bb1 = smb + 32768 + (uint32_t)(((g + 1) * 16 + rB) * 128);
                ldsm4(kh1, bb1 + boff);
                ldsm4(kl1, bb1 + 16384 + boff);
            }
            // interleaved: 4 (or 8) independent acc chains per pass
            mma16816(S[2 * g],     qh, &kh0[0]);
            mma16816(S[2 * g + 1], qh, &kh0[2]);
            if (g1ok) { mma16816(S[2 * g + 2], qh, &kh1[0]);
                        mma16816(S[2 * g + 3], qh, &kh1[2]); }
            mma16816(S[2 * g],     qh, &kl0[0]);
            mma16816(S[2 * g + 1], qh, &kl0[2]);
            if (g1ok) { mma16816(S[2 * g + 2], qh, &kl1[0]);
                        mma16816(S[2 * g + 3], qh, &kl1[2]); }
            mma16816(S[2 * g],     ql, &kh0[0]);
            mma16816(S[2 * g + 1], ql, &kh0[2]);
            if (g1ok) { mma16816(S[2 * g + 2], ql, &kh1[0]);
                        mma16816(S[2 * g + 3], ql, &kh1[2]); }
        }
    }

    // ---------------- softmax (no max-subtract; scores ~N(0,1)) ----------------
    const int row0 = rb * 16 + (lane >> 2);
    const int row1 = row0 + 8;
    const int colb = 2 * (lane & 3);
    float sum0 = 0.f, sum1 = 0.f;
#pragma unroll
    for (int nf = 0; nf < 16; nf++) {
        if (nf > 2 * rb + 1) break;
        const int c0 = nf * 8 + colb, c1 = c0 + 1;
        float e00 = (c0 <= row0) ? __expf(S[nf][0] * 0.125f) : 0.f;
        float e01 = (c1 <= row0) ? __expf(S[nf][1] * 0.125f) : 0.f;
        float e10 = (c0 <= row1) ? __expf(S[nf][2] * 0.125f) : 0.f;
        float e11 = (c1 <= row1) ? __expf(S[nf][3] * 0.125f) : 0.f;
        S[nf][0] = e00; S[nf][1] = e01; S[nf][2] = e10; S[nf][3] = e11;
        sum0 += e00 + e01;
        sum1 += e10 + e11;
    }
    sum0 += __shfl_xor_sync(0xFFFFFFFFu, sum0, 1);
    sum0 += __shfl_xor_sync(0xFFFFFFFFu, sum0, 2);
    sum1 += __shfl_xor_sync(0xFFFFFFFFu, sum1, 1);
    sum1 += __shfl_xor_sync(0xFFFFFFFFu, sum1, 2);
    const float inv0 = 1.0f / sum0;
    const float inv1 = 1.0f / sum1;

    // ---------------- O = P @ V (3-split; V via ldmatrix.trans on [t][d]) --------
    float O[8][4];
#pragma unroll
    for (int i = 0; i < 8; i++)
#pragma unroll
        for (int e = 0; e < 4; e++) O[i][e] = 0.f;

    const int mT = lane >> 3;
    const int rT = lane & 7;

#pragma unroll
    for (int ks = 0; ks < 8; ks++) {
        if (ks > rb) break;
        uint32_t phi[4], plo[4];
        hilo_pair(S[2 * ks][0] * inv0,     S[2 * ks][1] * inv0,     phi[0], plo[0]);
        hilo_pair(S[2 * ks][2] * inv1,     S[2 * ks][3] * inv1,     phi[1], plo[1]);
        hilo_pair(S[2 * ks + 1][0] * inv0, S[2 * ks + 1][1] * inv0, phi[2], plo[2]);
        hilo_pair(S[2 * ks + 1][2] * inv1, S[2 * ks + 1][3] * inv1, phi[3], plo[3]);

        const int srow = ks * 16 + (mT & 1) * 8 + rT;
        const uint32_t rowOff = (uint32_t)(srow * 128);
        // load all V fragments for this ks, then 3 interleaved passes (8 accs)
        uint32_t vh[4][4], vl[4][4];
#pragma unroll
        for (int g = 0; g < 4; g++) {
            const int dseg = g * 2 + (mT >> 1);
            const uint32_t addr = rowOff + (uint32_t)(((dseg ^ (srow & 7)) << 4));
            ldsm4t(vh[g], smb + 65536 + addr);
            ldsm4t(vl[g], smb + 81920 + addr);
        }
#pragma unroll
        for (int g = 0; g < 4; g++) {
            mma16816(O[2 * g],     phi, &vh[g][0]);
            mma16816(O[2 * g + 1], phi, &vh[g][2]);
        }
#pragma unroll
        for (int g = 0; g < 4; g++) {
            mma16816(O[2 * g],     phi, &vl[g][0]);
            mma16816(O[2 * g + 1], phi, &vl[g][2]);
        }
#pragma unroll
        for (int g = 0; g < 4; g++) {
            mma16816(O[2 * g],     plo, &vh[g][0]);
            mma16816(O[2 * g + 1], plo, &vh[g][2]);
        }
    }

    // ---------------- epilogue: att bf16 hi/lo [b][t][h*64+d] ----------------
    const size_t obase = (size_t)b * T * HD + h * D;
#pragma unroll
    for (int nf = 0; nf < 8; nf++) {
        const int d0 = nf * 8 + colb;
        uint32_t hi, lo;
        hilo_pair(O[nf][0], O[nf][1], hi, lo);
        *(uint32_t*)(g_atthi + obase + (size_t)row0 * HD + d0) = hi;
        *(uint32_t*)(g_attlo + obase + (size_t)row0 * HD + d0) = lo;
        hilo_pair(O[nf][2], O[nf][3], hi, lo);
        *(uint32_t*)(g_atthi + obase + (size_t)row1 * HD + d0) = hi;
        *(uint32_t*)(g_attlo + obase + (size_t)row1 * HD + d0) = lo;
    }
}

// =================================================================================
extern "C" void kernel_launch(void* const* d_in, const int* in_sizes, int n_in,
                              void* d_out, int out_size)
{
    (void)in_sizes; (void)n_in; (void)out_size;
    const float* x  = (const float*)d_in[0];
    const float* Wq = (const float*)d_in[1];
    const float* Wk = (const float*)d_in[2];
    const float* Wv = (const float*)d_in[3];
    const float* Wp = (const float*)d_in[4];
    const float* bp = (const float*)d_in[5];
    float* out = (float*)d_out;

    cudaFuncSetAttribute(mma_gemm<false>, cudaFuncAttributeMaxDynamicSharedMemorySize, GEMM_SMEM);
    cudaFuncSetAttribute(mma_gemm<true>,  cudaFuncAttributeMaxDynamicSharedMemorySize, GEMM_SMEM);
    cudaFuncSetAttribute(attn_mma, cudaFuncAttributeMaxDynamicSharedMemorySize, ATTN_SMEM);

    conv_x_kernel<<<(BATCH * T * C / 4) / 256, 256>>>(x);
    conv_w_kernel<<<(NQKV * C + 255) / 256, 256>>>(Wq, Wk, Wv);
    conv_wp_kernel<<<(HD * C + 255) / 256, 256>>>(Wp);

    mma_gemm<false><<<dim3(18, BATCH), 256, GEMM_SMEM>>>(nullptr, nullptr);
    attn_mma<<<dim3(BATCH, H), 256, ATTN_SMEM>>>();
    mma_gemm<true><<<dim3(6, BATCH), 256, GEMM_SMEM>>>(bp, out);
}